// round 2
// baseline (speedup 1.0000x reference)
#include <cuda_runtime.h>
#include <math.h>

#define MTOT   16384      // B*N = 4*4096
#define DMODEL 1024
#define NHEADS 16
#define HDIM   64
#define BATCH  4
#define SEQ    4096
#define BH     (BATCH*NHEADS)   // 64

// ---------------- scratch (device globals: allocation-free) ----------------
// Reuse: attn lives in g_V (V dead after kv_ksum), Y lives in g_K (K dead
// after kv_ksum). Total scratch: 3 x 64MB + 1MB.
__device__ float g_Q[(size_t)MTOT*DMODEL];
__device__ float g_K[(size_t)MTOT*DMODEL];
__device__ float g_V[(size_t)MTOT*DMODEL];
__device__ float g_KV[BH*HDIM*HDIM];
__device__ float g_Ksum[BH*HDIM];

// ---------------- zero KV/Ksum (atomically accumulated each call) ----------
__global__ void zero_k(float* __restrict__ KV, float* __restrict__ Ksum) {
    int i = blockIdx.x * blockDim.x + threadIdx.x;
    if (i < BH*HDIM*HDIM) KV[i] = 0.f;
    if (i < BH*HDIM)      Ksum[i] = 0.f;
}

// ---------------- 128x128x16 tiled fp32 GEMM, 256 thr, 8x8 micro ----------
// C[M,N] = act(A[M,K] @ W[K,N] + bias)   MODE: 0 none, 1 elu, 2 +residual
template<int MODE>
__global__ __launch_bounds__(256) void gemm_k(
    const float* __restrict__ A, const float* __restrict__ W,
    const float* __restrict__ bias, const float* __restrict__ res,
    float* __restrict__ C)
{
    const int K = DMODEL, N = DMODEL;
    __shared__ __align__(16) float As[16][128];   // transposed: [k][m]
    __shared__ __align__(16) float Bs[16][128];   // [k][n]

    int tid  = threadIdx.x;
    int row0 = blockIdx.y * 128;
    int col0 = blockIdx.x * 128;
    int ty   = tid >> 4;        // 0..15 -> row group
    int tx   = tid & 15;        // 0..15 -> col group

    float acc[8][8];
    #pragma unroll
    for (int i = 0; i < 8; i++)
        #pragma unroll
        for (int j = 0; j < 8; j++) acc[i][j] = 0.f;

    int arow = tid >> 2;            // 0..63
    int acol = (tid & 3) * 4;       // 0,4,8,12
    int wrow = tid >> 5;            // 0..7
    int wcol = (tid & 31) * 4;      // 0..124

    for (int k0 = 0; k0 < K; k0 += 16) {
        #pragma unroll
        for (int r = 0; r < 2; r++) {
            float4 v = *(const float4*)&A[(size_t)(row0 + arow + r*64)*K + k0 + acol];
            As[acol+0][arow + r*64] = v.x;
            As[acol+1][arow + r*64] = v.y;
            As[acol+2][arow + r*64] = v.z;
            As[acol+3][arow + r*64] = v.w;
        }
        #pragma unroll
        for (int r = 0; r < 2; r++) {
            *(float4*)&Bs[wrow + r*8][wcol] =
                *(const float4*)&W[(size_t)(k0 + wrow + r*8)*N + col0 + wcol];
        }
        __syncthreads();

        #pragma unroll
        for (int kk = 0; kk < 16; kk++) {
            float a[8], b[8];
            #pragma unroll
            for (int i = 0; i < 8; i++) a[i] = As[kk][ty*8 + i];
            #pragma unroll
            for (int j = 0; j < 8; j++) b[j] = Bs[kk][tx*8 + j];
            #pragma unroll
            for (int i = 0; i < 8; i++)
                #pragma unroll
                for (int j = 0; j < 8; j++)
                    acc[i][j] += a[i] * b[j];
        }
        __syncthreads();
    }

    float bv[8];
    #pragma unroll
    for (int j = 0; j < 8; j++) bv[j] = bias[col0 + tx*8 + j];

    #pragma unroll
    for (int i = 0; i < 8; i++) {
        int row = row0 + ty*8 + i;
        #pragma unroll
        for (int j = 0; j < 8; j++) {
            int col = col0 + tx*8 + j;
            float v = acc[i][j] + bv[j];
            if (MODE == 1) v = (v > 0.f) ? v : (expf(v) - 1.f);
            if (MODE == 2) v += res[(size_t)row*N + col];
            C[(size_t)row*N + col] = v;
        }
    }
}

// ---------------- KV[d,e] = sum_n K[n,d] V[n,e] ; Ksum[d] = sum_n K[n,d] --
// grid: (8 chunks of 512 rows, BH). fp32 atomic combine into 1MB buffer.
__global__ __launch_bounds__(256) void kv_ksum_k(
    const float* __restrict__ Km, const float* __restrict__ Vm,
    float* __restrict__ KVg, float* __restrict__ Ksumg)
{
    __shared__ __align__(16) float Ks[16][64];
    __shared__ __align__(16) float Vs[16][64];
    int tid = threadIdx.x;
    int bh  = blockIdx.y;
    int b   = bh >> 4, h = bh & 15;
    int rbase = b*SEQ + blockIdx.x * 512;
    int cbase = h*HDIM;
    int td = tid >> 4, te = tid & 15;
    int lrow = tid >> 4;           // 0..15
    int lcol = (tid & 15) * 4;     // 0..60

    float acc[4][4] = {};
    float myk = 0.f;

    for (int t = 0; t < 512; t += 16) {
        *(float4*)&Ks[lrow][lcol] =
            *(const float4*)&Km[(size_t)(rbase + t + lrow)*DMODEL + cbase + lcol];
        *(float4*)&Vs[lrow][lcol] =
            *(const float4*)&Vm[(size_t)(rbase + t + lrow)*DMODEL + cbase + lcol];
        __syncthreads();

        #pragma unroll
        for (int kk = 0; kk < 16; kk++) {
            float kd[4], ve[4];
            #pragma unroll
            for (int i = 0; i < 4; i++) kd[i] = Ks[kk][td*4 + i];
            #pragma unroll
            for (int j = 0; j < 4; j++) ve[j] = Vs[kk][te*4 + j];
            #pragma unroll
            for (int i = 0; i < 4; i++)
                #pragma unroll
                for (int j = 0; j < 4; j++)
                    acc[i][j] += kd[i] * ve[j];
        }
        if (tid < 64) {
            #pragma unroll
            for (int kk = 0; kk < 16; kk++) myk += Ks[kk][tid];
        }
        __syncthreads();
    }

    float* KVb = KVg + (size_t)bh*HDIM*HDIM;
    #pragma unroll
    for (int i = 0; i < 4; i++)
        #pragma unroll
        for (int j = 0; j < 4; j++)
            atomicAdd(&KVb[(td*4 + i)*HDIM + te*4 + j], acc[i][j]);
    if (tid < 64) atomicAdd(&Ksumg[bh*HDIM + tid], myk);
}

// ---------------- out[n,e] = z[n] * sum_d Q[n,d] KV[d,e],  z=1/(Q.Ksum) ---
// grid: (SEQ/64 tiles, BH). 64x64 tile per block.
__global__ __launch_bounds__(256) void qattn_k(
    const float* __restrict__ Qm, const float* __restrict__ KVg,
    const float* __restrict__ Ksumg, float* __restrict__ attn)
{
    __shared__ float Qs[64][65];                 // padded: kills 8-way conflict
    __shared__ __align__(16) float KVs[64][64];
    __shared__ float Ksums[64];
    __shared__ float zs[64];

    int tid = threadIdx.x;
    int bh  = blockIdx.y;
    int b   = bh >> 4, h = bh & 15;
    int rbase = b*SEQ + blockIdx.x * 64;
    int cbase = h*HDIM;

    int qrow = tid >> 2;          // 0..63
    int qc0  = (tid & 3) * 16;    // 0,16,32,48
    #pragma unroll
    for (int c = 0; c < 16; c += 4) {
        float4 v = *(const float4*)&Qm[(size_t)(rbase + qrow)*DMODEL + cbase + qc0 + c];
        Qs[qrow][qc0+c+0] = v.x;  Qs[qrow][qc0+c+1] = v.y;
        Qs[qrow][qc0+c+2] = v.z;  Qs[qrow][qc0+c+3] = v.w;
    }
    const float* KVb = KVg + (size_t)bh*HDIM*HDIM;
    #pragma unroll
    for (int c = 0; c < 16; c += 4)
        *(float4*)&KVs[qrow][qc0 + c] = *(const float4*)&KVb[qrow*64 + qc0 + c];
    if (tid < 64) Ksums[tid] = Ksumg[bh*HDIM + tid];
    __syncthreads();

    if (tid < 64) {
        float s = 0.f;
        #pragma unroll
        for (int d = 0; d < 64; d++) s += Qs[tid][d] * Ksums[d];
        zs[tid] = 1.f / s;
    }
    __syncthreads();

    int td = tid >> 4, te = tid & 15;
    float acc[4][4] = {};
    #pragma unroll
    for (int d = 0; d < 64; d++) {
        float q[4], kv[4];
        #pragma unroll
        for (int i = 0; i < 4; i++) q[i]  = Qs[td*4 + i][d];
        #pragma unroll
        for (int j = 0; j < 4; j++) kv[j] = KVs[d][te*4 + j];
        #pragma unroll
        for (int i = 0; i < 4; i++)
            #pragma unroll
            for (int j = 0; j < 4; j++)
                acc[i][j] += q[i] * kv[j];
    }
    #pragma unroll
    for (int i = 0; i < 4; i++) {
        int r = td*4 + i;
        float z = zs[r];
        #pragma unroll
        for (int j = 0; j < 4; j++)
            attn[(size_t)(rbase + r)*DMODEL + cbase + te*4 + j] = acc[i][j] * z;
    }
}

// ---------------- LayerNorm over D=1024, one block per row ----------------
__global__ __launch_bounds__(256) void ln_k(
    const float* __restrict__ Y, const float* __restrict__ gamma,
    const float* __restrict__ beta, float* __restrict__ out)
{
    int row = blockIdx.x;
    int tid = threadIdx.x;
    float4 v = *(const float4*)&Y[(size_t)row*DMODEL + tid*4];
    float s  = v.x + v.y + v.z + v.w;
    float sq = v.x*v.x + v.y*v.y + v.z*v.z + v.w*v.w;
    #pragma unroll
    for (int o = 16; o > 0; o >>= 1) {
        s  += __shfl_xor_sync(0xFFFFFFFFu, s,  o);
        sq += __shfl_xor_sync(0xFFFFFFFFu, sq, o);
    }
    __shared__ float ss[8], ssq[8];
    int w = tid >> 5, l = tid & 31;
    if (l == 0) { ss[w] = s; ssq[w] = sq; }
    __syncthreads();
    if (tid == 0) {
        float S = 0.f, SQ = 0.f;
        #pragma unroll
        for (int i = 0; i < 8; i++) { S += ss[i]; SQ += ssq[i]; }
        ss[0] = S; ssq[0] = SQ;
    }
    __syncthreads();
    float mu  = ss[0] * (1.f/1024.f);
    float var = ssq[0] * (1.f/1024.f) - mu*mu;
    float inv = rsqrtf(var + 1e-3f);
    float4 g  = *(const float4*)&gamma[tid*4];
    float4 be = *(const float4*)&beta[tid*4];
    float4 o;
    o.x = (v.x - mu)*inv*g.x + be.x;
    o.y = (v.y - mu)*inv*g.y + be.y;
    o.z = (v.z - mu)*inv*g.z + be.z;
    o.w = (v.w - mu)*inv*g.w + be.w;
    *(float4*)&out[(size_t)row*DMODEL + tid*4] = o;
}

// ---------------- host entry ----------------------------------------------
extern "C" void kernel_launch(void* const* d_in, const int* in_sizes, int n_in,
                              void* d_out, int out_size)
{
    const float* x     = (const float*)d_in[0];
    const float* Wq    = (const float*)d_in[1];
    const float* bq    = (const float*)d_in[2];
    const float* Wk    = (const float*)d_in[3];
    const float* bk    = (const float*)d_in[4];
    const float* Wv    = (const float*)d_in[5];
    const float* bv    = (const float*)d_in[6];
    const float* Wo    = (const float*)d_in[7];
    const float* bo    = (const float*)d_in[8];
    const float* gamma = (const float*)d_in[9];
    const float* beta  = (const float*)d_in[10];
    float* out = (float*)d_out;

    float *Q, *K, *V, *KV, *Ksum;
    cudaGetSymbolAddress((void**)&Q,    g_Q);
    cudaGetSymbolAddress((void**)&K,    g_K);
    cudaGetSymbolAddress((void**)&V,    g_V);
    cudaGetSymbolAddress((void**)&KV,   g_KV);
    cudaGetSymbolAddress((void**)&Ksum, g_Ksum);

    float* attn = V;   // V dead after kv_ksum_k
    float* Y    = K;   // K dead after kv_ksum_k

    dim3 gg(DMODEL/128, MTOT/128);   // (8, 128)

    zero_k<<<(BH*HDIM*HDIM + 255)/256, 256>>>(KV, Ksum);
    gemm_k<1><<<gg, 256>>>(x, Wq, bq, nullptr, Q);      // Q = elu(xWq + bq)
    gemm_k<1><<<gg, 256>>>(x, Wk, bk, nullptr, K);      // K = elu(xWk + bk)
    gemm_k<0><<<gg, 256>>>(x, Wv, bv, nullptr, V);      // V = xWv + bv
    kv_ksum_k<<<dim3(8, BH), 256>>>(K, V, KV, Ksum);
    qattn_k<<<dim3(SEQ/64, BH), 256>>>(Q, KV, Ksum, attn);
    gemm_k<2><<<gg, 256>>>(attn, Wo, bo, x, Y);         // Y = x + attn Wo + bo
    ln_k<<<MTOT, 256>>>(Y, gamma, beta, out);
}

// round 4
// speedup vs baseline: 1.9030x; 1.9030x over previous
#include <cuda_runtime.h>
#include <cuda_bf16.h>
#include <math.h>
#include <stdint.h>

#define MTOT   16384      // B*N = 4*4096
#define DMODEL 1024
#define NHEADS 16
#define HDIM   64
#define BATCH  4
#define SEQ    4096
#define BH     (BATCH*NHEADS)   // 64

// ---------------- scratch (device globals: allocation-free) ----------------
__device__ float g_Q[(size_t)MTOT*DMODEL];
__device__ float g_K[(size_t)MTOT*DMODEL];
__device__ float g_V[(size_t)MTOT*DMODEL];
__device__ float g_KV[BH*HDIM*HDIM];
__device__ float g_Ksum[BH*HDIM];
// bf16 split buffers: activations (x, later attn) and transposed weights
__device__ __nv_bfloat16 g_Ah[(size_t)MTOT*DMODEL];
__device__ __nv_bfloat16 g_Al[(size_t)MTOT*DMODEL];
__device__ __nv_bfloat16 g_WTh[4ULL*DMODEL*DMODEL];   // [w][n][k]
__device__ __nv_bfloat16 g_WTl[4ULL*DMODEL*DMODEL];

__device__ __forceinline__ void split2(float x, __nv_bfloat16& h, __nv_bfloat16& l) {
    h = __float2bfloat16_rn(x);
    l = __float2bfloat16_rn(x - __bfloat162float(h));
}

// ---------------- zero KV/Ksum ---------------------------------------------
__global__ void zero_k(float* __restrict__ KV, float* __restrict__ Ksum) {
    int i = blockIdx.x * blockDim.x + threadIdx.x;
    if (i < BH*HDIM*HDIM) KV[i] = 0.f;
    if (i < BH*HDIM)      Ksum[i] = 0.f;
}

// ---------------- split fp32 row-major -> bf16 hi/lo (same layout) ---------
__global__ __launch_bounds__(256) void split_rm(
    const float* __restrict__ in, __nv_bfloat16* __restrict__ H,
    __nv_bfloat16* __restrict__ L, int n4)
{
    for (int i = blockIdx.x*blockDim.x + threadIdx.x; i < n4; i += gridDim.x*blockDim.x) {
        float4 v = ((const float4*)in)[i];
        __nv_bfloat16 h0,h1,h2,h3,l0,l1,l2,l3;
        split2(v.x,h0,l0); split2(v.y,h1,l1); split2(v.z,h2,l2); split2(v.w,h3,l3);
        __nv_bfloat162* Hp = (__nv_bfloat162*)H;
        __nv_bfloat162* Lp = (__nv_bfloat162*)L;
        Hp[i*2+0] = __nv_bfloat162{h0,h1}; Hp[i*2+1] = __nv_bfloat162{h2,h3};
        Lp[i*2+0] = __nv_bfloat162{l0,l1}; Lp[i*2+1] = __nv_bfloat162{l2,l3};
    }
}

// ---------------- split + transpose: W[K][N] -> WT[N][K] bf16 hi/lo --------
__global__ __launch_bounds__(256) void split_tr(
    const float* __restrict__ W, __nv_bfloat16* __restrict__ Th,
    __nv_bfloat16* __restrict__ Tl)
{
    __shared__ float tile[32][33];
    int tx = threadIdx.x, ty = threadIdx.y;            // (32, 8)
    int k0 = blockIdx.y * 32, n0 = blockIdx.x * 32;
    #pragma unroll
    for (int i = 0; i < 32; i += 8)
        tile[ty+i][tx] = W[(size_t)(k0+ty+i)*DMODEL + n0 + tx];
    __syncthreads();
    #pragma unroll
    for (int i = 0; i < 32; i += 8) {
        float v = tile[tx][ty+i];
        __nv_bfloat16 h, l; split2(v, h, l);
        size_t o = (size_t)(n0+ty+i)*DMODEL + k0 + tx;
        Th[o] = h; Tl[o] = l;
    }
}

// ---------------- bf16-split tensor-core GEMM ------------------------------
// C[M,N] = act( A @ W + bias ),  A given as hi/lo bf16 row-major [M][K],
// W given as hi/lo bf16 TRANSPOSED [N][K].  3 products: hh + hl + lh.
// MODE: 0 none, 1 elu, 2 +residual
#define BM 128
#define BN 128
#define BK 16
#define PIT 24    // smem pitch (elems): gid*12+tig words cover 32 banks

__device__ __forceinline__ void cp16(uint32_t dst, const void* src) {
    asm volatile("cp.async.cg.shared.global [%0], [%1], 16;\n" :: "r"(dst), "l"(src));
}
__device__ __forceinline__ void cp_commit() { asm volatile("cp.async.commit_group;\n"); }
template<int N> __device__ __forceinline__ void cp_wait() {
    asm volatile("cp.async.wait_group %0;\n" :: "n"(N));
}
__device__ __forceinline__ void mma_bf16(float c[4],
    uint32_t a0, uint32_t a1, uint32_t a2, uint32_t a3, uint32_t b0, uint32_t b1) {
    asm volatile(
        "mma.sync.aligned.m16n8k16.row.col.f32.bf16.bf16.f32 "
        "{%0,%1,%2,%3}, {%4,%5,%6,%7}, {%8,%9}, {%0,%1,%2,%3};"
        : "+f"(c[0]), "+f"(c[1]), "+f"(c[2]), "+f"(c[3])
        : "r"(a0), "r"(a1), "r"(a2), "r"(a3), "r"(b0), "r"(b1));
}

template<int MODE>
__global__ __launch_bounds__(256, 2) void gemm_bs(
    const __nv_bfloat16* __restrict__ Ahg, const __nv_bfloat16* __restrict__ Alg,
    const __nv_bfloat16* __restrict__ BTh, const __nv_bfloat16* __restrict__ BTl,
    const float* __restrict__ bias, const float* __restrict__ res,
    float* __restrict__ C)
{
    const int K = DMODEL, N = DMODEL;
    __shared__ __align__(16) __nv_bfloat16 Ah[2][BM][PIT];
    __shared__ __align__(16) __nv_bfloat16 Al[2][BM][PIT];
    __shared__ __align__(16) __nv_bfloat16 Bh[2][BN][PIT];
    __shared__ __align__(16) __nv_bfloat16 Bl[2][BN][PIT];

    int tid  = threadIdx.x;
    int row0 = blockIdx.y * BM;
    int col0 = blockIdx.x * BN;

    int w    = tid >> 5;
    int lane = tid & 31;
    int wm   = (w & 1) * 64;
    int wn   = (w >> 1) * 32;
    int g    = lane >> 2;       // 0..7
    int tq   = lane & 3;        // 0..3

    int lrow = tid >> 1;        // 0..127
    int lch  = (tid & 1) * 8;   // 0 or 8 (elems)

    float acc[4][4][4];
    #pragma unroll
    for (int i = 0; i < 4; i++)
        #pragma unroll
        for (int j = 0; j < 4; j++)
            #pragma unroll
            for (int e = 0; e < 4; e++) acc[i][j][e] = 0.f;

    uint32_t sAh = (uint32_t)__cvta_generic_to_shared(&Ah[0][0][0]);
    uint32_t sAl = (uint32_t)__cvta_generic_to_shared(&Al[0][0][0]);
    uint32_t sBh = (uint32_t)__cvta_generic_to_shared(&Bh[0][0][0]);
    uint32_t sBl = (uint32_t)__cvta_generic_to_shared(&Bl[0][0][0]);
    const uint32_t stg = BM * PIT * 2;                  // bytes per stage
    const uint32_t dof = (lrow * PIT + lch) * 2;        // dest offset in stage

    const __nv_bfloat16* aH = Ahg + (size_t)(row0 + lrow)*K + lch;
    const __nv_bfloat16* aL = Alg + (size_t)(row0 + lrow)*K + lch;
    const __nv_bfloat16* bH = BTh + (size_t)(col0 + lrow)*K + lch;
    const __nv_bfloat16* bL = BTl + (size_t)(col0 + lrow)*K + lch;

    auto issue = [&](int stage, int k0) {
        cp16(sAh + stage*stg + dof, aH + k0);
        cp16(sAl + stage*stg + dof, aL + k0);
        cp16(sBh + stage*stg + dof, bH + k0);
        cp16(sBl + stage*stg + dof, bL + k0);
    };

    const int NITER = DMODEL / BK;   // 64
    issue(0, 0); cp_commit();

    for (int it = 0; it < NITER; it++) {
        int st = it & 1;
        if (it + 1 < NITER) { issue(st ^ 1, (it+1)*BK); cp_commit(); cp_wait<1>(); }
        else                { cp_wait<0>(); }
        __syncthreads();

        uint32_t af[4][4], bf[4][2];
        // ---- load A_hi, B_hi; product hi*hi
        #pragma unroll
        for (int mt = 0; mt < 4; mt++) {
            int r = wm + mt*16 + g;
            af[mt][0] = *(const uint32_t*)&Ah[st][r  ][2*tq];
            af[mt][1] = *(const uint32_t*)&Ah[st][r+8][2*tq];
            af[mt][2] = *(const uint32_t*)&Ah[st][r  ][2*tq+8];
            af[mt][3] = *(const uint32_t*)&Ah[st][r+8][2*tq+8];
        }
        #pragma unroll
        for (int nt = 0; nt < 4; nt++) {
            int c = wn + nt*8 + g;
            bf[nt][0] = *(const uint32_t*)&Bh[st][c][2*tq];
            bf[nt][1] = *(const uint32_t*)&Bh[st][c][2*tq+8];
        }
        #pragma unroll
        for (int mt = 0; mt < 4; mt++)
            #pragma unroll
            for (int nt = 0; nt < 4; nt++)
                mma_bf16(acc[mt][nt], af[mt][0],af[mt][1],af[mt][2],af[mt][3],
                         bf[nt][0], bf[nt][1]);
        // ---- B_lo; product hi*lo
        #pragma unroll
        for (int nt = 0; nt < 4; nt++) {
            int c = wn + nt*8 + g;
            bf[nt][0] = *(const uint32_t*)&Bl[st][c][2*tq];
            bf[nt][1] = *(const uint32_t*)&Bl[st][c][2*tq+8];
        }
        #pragma unroll
        for (int mt = 0; mt < 4; mt++)
            #pragma unroll
            for (int nt = 0; nt < 4; nt++)
                mma_bf16(acc[mt][nt], af[mt][0],af[mt][1],af[mt][2],af[mt][3],
                         bf[nt][0], bf[nt][1]);
        // ---- A_lo, B_hi; product lo*hi
        #pragma unroll
        for (int mt = 0; mt < 4; mt++) {
            int r = wm + mt*16 + g;
            af[mt][0] = *(const uint32_t*)&Al[st][r  ][2*tq];
            af[mt][1] = *(const uint32_t*)&Al[st][r+8][2*tq];
            af[mt][2] = *(const uint32_t*)&Al[st][r  ][2*tq+8];
            af[mt][3] = *(const uint32_t*)&Al[st][r+8][2*tq+8];
        }
        #pragma unroll
        for (int nt = 0; nt < 4; nt++) {
            int c = wn + nt*8 + g;
            bf[nt][0] = *(const uint32_t*)&Bh[st][c][2*tq];
            bf[nt][1] = *(const uint32_t*)&Bh[st][c][2*tq+8];
        }
        #pragma unroll
        for (int mt = 0; mt < 4; mt++)
            #pragma unroll
            for (int nt = 0; nt < 4; nt++)
                mma_bf16(acc[mt][nt], af[mt][0],af[mt][1],af[mt][2],af[mt][3],
                         bf[nt][0], bf[nt][1]);
        __syncthreads();
    }

    // epilogue: c0,c1 -> (row g, cols 2tq..2tq+1); c2,c3 -> row g+8
    #pragma unroll
    for (int mt = 0; mt < 4; mt++) {
        #pragma unroll
        for (int nt = 0; nt < 4; nt++) {
            int r = row0 + wm + mt*16 + g;
            int c = col0 + wn + nt*8 + tq*2;
            float b0 = bias[c], b1 = bias[c+1];
            #pragma unroll
            for (int h = 0; h < 2; h++) {
                int rr = r + h*8;
                float v0 = acc[mt][nt][h*2+0] + b0;
                float v1 = acc[mt][nt][h*2+1] + b1;
                if (MODE == 1) {
                    v0 = (v0 > 0.f) ? v0 : expm1f(v0);
                    v1 = (v1 > 0.f) ? v1 : expm1f(v1);
                }
                if (MODE == 2) {
                    const float2 rv = *(const float2*)&res[(size_t)rr*N + c];
                    v0 += rv.x; v1 += rv.y;
                }
                *(float2*)&C[(size_t)rr*N + c] = make_float2(v0, v1);
            }
        }
    }
}

// ---------------- KV[d,e] = sum_n K[n,d] V[n,e] ; Ksum[d] = sum_n K[n,d] --
__global__ __launch_bounds__(256) void kv_ksum_k(
    const float* __restrict__ Km, const float* __restrict__ Vm,
    float* __restrict__ KVg, float* __restrict__ Ksumg)
{
    __shared__ __align__(16) float Ks[16][64];
    __shared__ __align__(16) float Vs[16][64];
    int tid = threadIdx.x;
    int bh  = blockIdx.y;
    int b   = bh >> 4, h = bh & 15;
    int rbase = b*SEQ + blockIdx.x * 512;
    int cbase = h*HDIM;
    int td = tid >> 4, te = tid & 15;
    int lrow = tid >> 4;
    int lcol = (tid & 15) * 4;

    float acc[4][4] = {};
    float myk = 0.f;

    for (int t = 0; t < 512; t += 16) {
        *(float4*)&Ks[lrow][lcol] =
            *(const float4*)&Km[(size_t)(rbase + t + lrow)*DMODEL + cbase + lcol];
        *(float4*)&Vs[lrow][lcol] =
            *(const float4*)&Vm[(size_t)(rbase + t + lrow)*DMODEL + cbase + lcol];
        __syncthreads();

        #pragma unroll
        for (int kk = 0; kk < 16; kk++) {
            float kd[4], ve[4];
            #pragma unroll
            for (int i = 0; i < 4; i++) kd[i] = Ks[kk][td*4 + i];
            #pragma unroll
            for (int j = 0; j < 4; j++) ve[j] = Vs[kk][te*4 + j];
            #pragma unroll
            for (int i = 0; i < 4; i++)
                #pragma unroll
                for (int j = 0; j < 4; j++)
                    acc[i][j] += kd[i] * ve[j];
        }
        if (tid < 64) {
            #pragma unroll
            for (int kk = 0; kk < 16; kk++) myk += Ks[kk][tid];
        }
        __syncthreads();
    }

    float* KVb = KVg + (size_t)bh*HDIM*HDIM;
    #pragma unroll
    for (int i = 0; i < 4; i++)
        #pragma unroll
        for (int j = 0; j < 4; j++)
            atomicAdd(&KVb[(td*4 + i)*HDIM + te*4 + j], acc[i][j]);
    if (tid < 64) atomicAdd(&Ksumg[bh*HDIM + tid], myk);
}

// ---------------- out[n,e] = z[n] * sum_d Q[n,d] KV[d,e],  z=1/(Q.Ksum) ---
__global__ __launch_bounds__(256) void qattn_k(
    const float* __restrict__ Qm, const float* __restrict__ KVg,
    const float* __restrict__ Ksumg, float* __restrict__ attn)
{
    __shared__ float Qs[64][65];
    __shared__ __align__(16) float KVs[64][64];
    __shared__ float Ksums[64];
    __shared__ float zs[64];

    int tid = threadIdx.x;
    int bh  = blockIdx.y;
    int b   = bh >> 4, h = bh & 15;
    int rbase = b*SEQ + blockIdx.x * 64;
    int cbase = h*HDIM;

    int qrow = tid >> 2;
    int qc0  = (tid & 3) * 16;
    #pragma unroll
    for (int c = 0; c < 16; c += 4) {
        float4 v = *(const float4*)&Qm[(size_t)(rbase + qrow)*DMODEL + cbase + qc0 + c];
        Qs[qrow][qc0+c+0] = v.x;  Qs[qrow][qc0+c+1] = v.y;
        Qs[qrow][qc0+c+2] = v.z;  Qs[qrow][qc0+c+3] = v.w;
    }
    const float* KVb = KVg + (size_t)bh*HDIM*HDIM;
    #pragma unroll
    for (int c = 0; c < 16; c += 4)
        *(float4*)&KVs[qrow][qc0 + c] = *(const float4*)&KVb[qrow*64 + qc0 + c];
    if (tid < 64) Ksums[tid] = Ksumg[bh*HDIM + tid];
    __syncthreads();

    if (tid < 64) {
        float s = 0.f;
        #pragma unroll
        for (int d = 0; d < 64; d++) s += Qs[tid][d] * Ksums[d];
        zs[tid] = 1.f / s;
    }
    __syncthreads();

    int td = tid >> 4, te = tid & 15;
    float acc[4][4] = {};
    #pragma unroll
    for (int d = 0; d < 64; d++) {
        float q[4], kv[4];
        #pragma unroll
        for (int i = 0; i < 4; i++) q[i]  = Qs[td*4 + i][d];
        #pragma unroll
        for (int j = 0; j < 4; j++) kv[j] = KVs[d][te*4 + j];
        #pragma unroll
        for (int i = 0; i < 4; i++)
            #pragma unroll
            for (int j = 0; j < 4; j++)
                acc[i][j] += q[i] * kv[j];
    }
    #pragma unroll
    for (int i = 0; i < 4; i++) {
        int r = td*4 + i;
        float z = zs[r];
        #pragma unroll
        for (int j = 0; j < 4; j++)
            attn[(size_t)(rbase + r)*DMODEL + cbase + te*4 + j] = acc[i][j] * z;
    }
}

// ---------------- LayerNorm over D=1024 ------------------------------------
__global__ __launch_bounds__(256) void ln_k(
    const float* __restrict__ Y, const float* __restrict__ gamma,
    const float* __restrict__ beta, float* __restrict__ out)
{
    int row = blockIdx.x;
    int tid = threadIdx.x;
    float4 v = *(const float4*)&Y[(size_t)row*DMODEL + tid*4];
    float s  = v.x + v.y + v.z + v.w;
    float sq = v.x*v.x + v.y*v.y + v.z*v.z + v.w*v.w;
    #pragma unroll
    for (int o = 16; o > 0; o >>= 1) {
        s  += __shfl_xor_sync(0xFFFFFFFFu, s,  o);
        sq += __shfl_xor_sync(0xFFFFFFFFu, sq, o);
    }
    __shared__ float ss[8], ssq[8];
    int w = tid >> 5, l = tid & 31;
    if (l == 0) { ss[w] = s; ssq[w] = sq; }
    __syncthreads();
    if (tid == 0) {
        float S = 0.f, SQ = 0.f;
        #pragma unroll
        for (int i = 0; i < 8; i++) { S += ss[i]; SQ += ssq[i]; }
        ss[0] = S; ssq[0] = SQ;
    }
    __syncthreads();
    float mu  = ss[0] * (1.f/1024.f);
    float var = ssq[0] * (1.f/1024.f) - mu*mu;
    float inv = rsqrtf(var + 1e-3f);
    float4 gm = *(const float4*)&gamma[tid*4];
    float4 be = *(const float4*)&beta[tid*4];
    float4 o;
    o.x = (v.x - mu)*inv*gm.x + be.x;
    o.y = (v.y - mu)*inv*gm.y + be.y;
    o.z = (v.z - mu)*inv*gm.z + be.z;
    o.w = (v.w - mu)*inv*gm.w + be.w;
    *(float4*)&out[(size_t)row*DMODEL + tid*4] = o;
}

// ---------------- host entry ------------------------------------------------
extern "C" void kernel_launch(void* const* d_in, const int* in_sizes, int n_in,
                              void* d_out, int out_size)
{
    const float* x     = (const float*)d_in[0];
    const float* Wq    = (const float*)d_in[1];
    const float* bq    = (const float*)d_in[2];
    const float* Wk    = (const float*)d_in[3];
    const float* bk    = (const float*)d_in[4];
    const float* Wv    = (const float*)d_in[5];
    const float* bv    = (const float*)d_in[6];
    const float* Wo    = (const float*)d_in[7];
    const float* bo    = (const float*)d_in[8];
    const float* gamma = (const float*)d_in[9];
    const float* beta  = (const float*)d_in[10];
    float* out = (float*)d_out;

    float *Q, *K, *V, *KV, *Ksum;
    __nv_bfloat16 *Ah, *Al, *WTh, *WTl;
    cudaGetSymbolAddress((void**)&Q,    g_Q);
    cudaGetSymbolAddress((void**)&K,    g_K);
    cudaGetSymbolAddress((void**)&V,    g_V);
    cudaGetSymbolAddress((void**)&KV,   g_KV);
    cudaGetSymbolAddress((void**)&Ksum, g_Ksum);
    cudaGetSymbolAddress((void**)&Ah,   g_Ah);
    cudaGetSymbolAddress((void**)&Al,   g_Al);
    cudaGetSymbolAddress((void**)&WTh,  g_WTh);
    cudaGetSymbolAddress((void**)&WTl,  g_WTl);

    float* attn = V;   // V dead after kv_ksum_k
    float* Y    = K;   // K dead after kv_ksum_k
    const size_t WSZ = (size_t)DMODEL*DMODEL;

    dim3 gg(DMODEL/BN, MTOT/BM);     // (8, 128)
    dim3 tb(32, 8);
    dim3 tg(DMODEL/32, DMODEL/32);   // (32, 32)
    const int N4 = MTOT*DMODEL/4;

    zero_k<<<(BH*HDIM*HDIM + 255)/256, 256>>>(KV, Ksum);
    split_rm<<<2048, 256>>>(x, Ah, Al, N4);
    split_tr<<<tg, tb>>>(Wq, WTh + 0*WSZ, WTl + 0*WSZ);
    split_tr<<<tg, tb>>>(Wk, WTh + 1*WSZ, WTl + 1*WSZ);
    split_tr<<<tg, tb>>>(Wv, WTh + 2*WSZ, WTl + 2*WSZ);
    split_tr<<<tg, tb>>>(Wo, WTh + 3*WSZ, WTl + 3*WSZ);

    gemm_bs<1><<<gg, 256>>>(Ah, Al, WTh + 0*WSZ, WTl + 0*WSZ, bq, nullptr, Q);
    gemm_bs<1><<<gg, 256>>>(Ah, Al, WTh + 1*WSZ, WTl + 1*WSZ, bk, nullptr, K);
    gemm_bs<0><<<gg, 256>>>(Ah, Al, WTh + 2*WSZ, WTl + 2*WSZ, bv, nullptr, V);

    kv_ksum_k<<<dim3(8, BH), 256>>>(K, V, KV, Ksum);
    qattn_k<<<dim3(SEQ/64, BH), 256>>>(Q, KV, Ksum, attn);

    split_rm<<<2048, 256>>>(attn, Ah, Al, N4);   // reuse split buffers
    gemm_bs<2><<<gg, 256>>>(Ah, Al, WTh + 3*WSZ, WTl + 3*WSZ, bo, x, Y);

    ln_k<<<MTOT, 256>>>(Y, gamma, beta, out);
}

// round 6
// speedup vs baseline: 2.3715x; 1.2462x over previous
#include <cuda_runtime.h>
#include <cuda_bf16.h>
#include <math.h>
#include <stdint.h>

#define MTOT   16384      // B*N = 4*4096
#define DMODEL 1024
#define NHEADS 16
#define HDIM   64
#define BATCH  4
#define SEQ    4096
#define BH     (BATCH*NHEADS)   // 64

// ---------------- scratch (device globals: allocation-free) ----------------
__device__ float g_Q[(size_t)MTOT*DMODEL];
__device__ float g_K[(size_t)MTOT*DMODEL];
__device__ float g_V[(size_t)MTOT*DMODEL];
__device__ float g_KV[BH*HDIM*HDIM];
__device__ float g_Ksum[BH*HDIM];
__device__ __nv_bfloat16 g_Ah[(size_t)MTOT*DMODEL];
__device__ __nv_bfloat16 g_Al[(size_t)MTOT*DMODEL];
__device__ __nv_bfloat16 g_WTh[4ULL*DMODEL*DMODEL];   // [w][n][k]
__device__ __nv_bfloat16 g_WTl[4ULL*DMODEL*DMODEL];

__device__ __forceinline__ void split2(float x, __nv_bfloat16& h, __nv_bfloat16& l) {
    h = __float2bfloat16_rn(x);
    l = __float2bfloat16_rn(x - __bfloat162float(h));
}

// ---------------- zero KV/Ksum ---------------------------------------------
__global__ void zero_k(float* __restrict__ KV, float* __restrict__ Ksum) {
    int i = blockIdx.x * blockDim.x + threadIdx.x;
    if (i < BH*HDIM*HDIM) KV[i] = 0.f;
    if (i < BH*HDIM)      Ksum[i] = 0.f;
}

// ---------------- split fp32 row-major -> bf16 hi/lo -----------------------
__global__ __launch_bounds__(256) void split_rm(
    const float* __restrict__ in, __nv_bfloat16* __restrict__ H,
    __nv_bfloat16* __restrict__ L, int n4)
{
    for (int i = blockIdx.x*blockDim.x + threadIdx.x; i < n4; i += gridDim.x*blockDim.x) {
        float4 v = ((const float4*)in)[i];
        __nv_bfloat16 h0,h1,h2,h3,l0,l1,l2,l3;
        split2(v.x,h0,l0); split2(v.y,h1,l1); split2(v.z,h2,l2); split2(v.w,h3,l3);
        __nv_bfloat162* Hp = (__nv_bfloat162*)H;
        __nv_bfloat162* Lp = (__nv_bfloat162*)L;
        Hp[i*2+0] = __nv_bfloat162{h0,h1}; Hp[i*2+1] = __nv_bfloat162{h2,h3};
        Lp[i*2+0] = __nv_bfloat162{l0,l1}; Lp[i*2+1] = __nv_bfloat162{l2,l3};
    }
}

// ---------------- split + transpose: W[K][N] -> WT[N][K] bf16 hi/lo --------
__global__ __launch_bounds__(256) void split_tr(
    const float* __restrict__ W, __nv_bfloat16* __restrict__ Th,
    __nv_bfloat16* __restrict__ Tl)
{
    __shared__ float tile[32][33];
    int tx = threadIdx.x, ty = threadIdx.y;            // (32, 8)
    int k0 = blockIdx.y * 32, n0 = blockIdx.x * 32;
    #pragma unroll
    for (int i = 0; i < 32; i += 8)
        tile[ty+i][tx] = W[(size_t)(k0+ty+i)*DMODEL + n0 + tx];
    __syncthreads();
    #pragma unroll
    for (int i = 0; i < 32; i += 8) {
        float v = tile[tx][ty+i];
        __nv_bfloat16 h, l; split2(v, h, l);
        size_t o = (size_t)(n0+ty+i)*DMODEL + k0 + tx;
        Th[o] = h; Tl[o] = l;
    }
}

// ---------------- bf16-split tensor-core GEMM (ldmatrix + BK=32) -----------
// C[M,N] = act( A @ W + bias ),  A hi/lo bf16 row-major [M][K],
// W hi/lo bf16 TRANSPOSED [N][K].  3 products: hh + hl + lh.
// MODE: 0 none, 1 elu, 2 +residual
#define BM 128
#define BN 128
#define BK 32
#define PIT 40                       // elems: 80B pitch -> conflict-free ldmatrix
#define STG_B (BM*PIT*2)             // 10240 bytes per stage per buffer
#define BUF_B (2*STG_B)              // 20480 bytes per buffer (2 stages)
#define GSMEM (4*BUF_B)              // 81920 total dynamic smem

__device__ __forceinline__ uint32_t s2u(const void* p) {
    uint32_t a;
    asm("{ .reg .u64 t; cvta.to.shared.u64 t, %1; cvt.u32.u64 %0, t; }"
        : "=r"(a) : "l"(p));
    return a;
}
__device__ __forceinline__ void cp16(uint32_t dst, const void* src) {
    asm volatile("cp.async.cg.shared.global [%0], [%1], 16;\n" :: "r"(dst), "l"(src));
}
__device__ __forceinline__ void cp_commit() { asm volatile("cp.async.commit_group;\n"); }
template<int N> __device__ __forceinline__ void cp_wait() {
    asm volatile("cp.async.wait_group %0;\n" :: "n"(N));
}
__device__ __forceinline__ void ldm_x4(uint32_t r[4], uint32_t addr) {
    asm volatile("ldmatrix.sync.aligned.m8n8.x4.shared.b16 {%0,%1,%2,%3}, [%4];"
        : "=r"(r[0]), "=r"(r[1]), "=r"(r[2]), "=r"(r[3]) : "r"(addr));
}
__device__ __forceinline__ void mma_bf16(float c[4],
    uint32_t a0, uint32_t a1, uint32_t a2, uint32_t a3, uint32_t b0, uint32_t b1) {
    asm volatile(
        "mma.sync.aligned.m16n8k16.row.col.f32.bf16.bf16.f32 "
        "{%0,%1,%2,%3}, {%4,%5,%6,%7}, {%8,%9}, {%0,%1,%2,%3};"
        : "+f"(c[0]), "+f"(c[1]), "+f"(c[2]), "+f"(c[3])
        : "r"(a0), "r"(a1), "r"(a2), "r"(a3), "r"(b0), "r"(b1));
}

template<int MODE>
__global__ __launch_bounds__(256, 2) void gemm_bs(
    const __nv_bfloat16* __restrict__ Ahg, const __nv_bfloat16* __restrict__ Alg,
    const __nv_bfloat16* __restrict__ BTh, const __nv_bfloat16* __restrict__ BTl,
    const float* __restrict__ bias, const float* __restrict__ res,
    float* __restrict__ C)
{
    extern __shared__ __align__(16) char smem[];
    const int K = DMODEL, N = DMODEL;
    uint32_t sb  = s2u(smem);
    const uint32_t bAh = sb + 0*BUF_B;
    const uint32_t bAl = sb + 1*BUF_B;
    const uint32_t bBh = sb + 2*BUF_B;
    const uint32_t bBl = sb + 3*BUF_B;

    int tid  = threadIdx.x;
    int row0 = blockIdx.y * BM;
    int col0 = blockIdx.x * BN;

    int w    = tid >> 5;
    int lane = tid & 31;
    int wm   = (w & 1) * 64;     // warp M origin
    int wn   = (w >> 1) * 32;    // warp N origin
    int g    = lane >> 2;        // 0..7
    int tq   = lane & 3;         // 0..3

    // ldmatrix per-lane addresses (byte offsets within a stage)
    // A: row = wm + (l&15), col = (l>>4)*8 ; per mt: +16 rows; per ks: +16 cols
    uint32_t aoffA = (uint32_t)(((wm + (lane & 15)) * PIT + (lane >> 4) * 8) * 2);
    // B: row = wn + (l&7) + (l>>4)*8, col = ((l>>3)&1)*8 ; per p(2 nt): +16 rows
    uint32_t aoffB = (uint32_t)(((wn + (lane & 7) + (lane >> 4) * 8) * PIT +
                                 ((lane >> 3) & 1) * 8) * 2);

    // cp.async coords: 512 16B-chunks per buffer per stage, 2 per thread
    int ch0 = tid, ch1 = tid + 256;
    int r0c = ch0 >> 2, c0c = ch0 & 3;   // row, 16B chunk
    int r1c = ch1 >> 2, c1c = ch1 & 3;

    const __nv_bfloat16* AhR = Ahg + (size_t)row0 * K;
    const __nv_bfloat16* AlR = Alg + (size_t)row0 * K;
    const __nv_bfloat16* BhR = BTh + (size_t)col0 * K;
    const __nv_bfloat16* BlR = BTl + (size_t)col0 * K;

    float acc[4][4][4];
    #pragma unroll
    for (int i = 0; i < 4; i++)
        #pragma unroll
        for (int j = 0; j < 4; j++)
            #pragma unroll
            for (int e = 0; e < 4; e++) acc[i][j][e] = 0.f;

    auto issue = [&](int st, int k0) {
        uint32_t d0 = (uint32_t)(st*STG_B + r0c*(PIT*2) + c0c*16);
        uint32_t d1 = (uint32_t)(st*STG_B + r1c*(PIT*2) + c1c*16);
        size_t g0 = (size_t)r0c*K + k0 + c0c*8;
        size_t g1 = (size_t)r1c*K + k0 + c1c*8;
        cp16(bAh + d0, AhR + g0);  cp16(bAh + d1, AhR + g1);
        cp16(bAl + d0, AlR + g0);  cp16(bAl + d1, AlR + g1);
        cp16(bBh + d0, BhR + g0);  cp16(bBh + d1, BhR + g1);
        cp16(bBl + d0, BlR + g0);  cp16(bBl + d1, BlR + g1);
        cp_commit();
    };

    const int NITER = K / BK;   // 32
    issue(0, 0);
    issue(1, BK);

    for (int it = 0; it < NITER; it++) {
        int st = it & 1;
        if (it + 2 < NITER) cp_wait<1>(); else cp_wait<0>();
        __syncthreads();

        uint32_t sA = st * STG_B;
        #pragma unroll
        for (int ks = 0; ks < 2; ks++) {
            uint32_t kso = ks * 32;             // 16 elems = 32B
            uint32_t af[4][4], bh[8], bl[8];
            // B hi/lo: 2 x ldmatrix.x4 each (covers nt pairs {0,1},{2,3})
            #pragma unroll
            for (int p = 0; p < 2; p++) {
                ldm_x4(&bh[p*4], bBh + sA + aoffB + p*(16*PIT*2) + kso);
                ldm_x4(&bl[p*4], bBl + sA + aoffB + p*(16*PIT*2) + kso);
            }
            // A hi
            #pragma unroll
            for (int mt = 0; mt < 4; mt++)
                ldm_x4(af[mt], bAh + sA + aoffA + mt*(16*PIT*2) + kso);
            // hh + hl
            #pragma unroll
            for (int mt = 0; mt < 4; mt++)
                #pragma unroll
                for (int nt = 0; nt < 4; nt++) {
                    mma_bf16(acc[mt][nt], af[mt][0],af[mt][1],af[mt][2],af[mt][3],
                             bh[nt*2], bh[nt*2+1]);
                    mma_bf16(acc[mt][nt], af[mt][0],af[mt][1],af[mt][2],af[mt][3],
                             bl[nt*2], bl[nt*2+1]);
                }
            // A lo (reuse regs) ; lh
            #pragma unroll
            for (int mt = 0; mt < 4; mt++)
                ldm_x4(af[mt], bAl + sA + aoffA + mt*(16*PIT*2) + kso);
            #pragma unroll
            for (int mt = 0; mt < 4; mt++)
                #pragma unroll
                for (int nt = 0; nt < 4; nt++)
                    mma_bf16(acc[mt][nt], af[mt][0],af[mt][1],af[mt][2],af[mt][3],
                             bh[nt*2], bh[nt*2+1]);
        }
        __syncthreads();
        if (it + 2 < NITER) issue(st, (it+2)*BK);
    }

    // epilogue: c0,c1 -> (row g, cols 2tq..2tq+1); c2,c3 -> row g+8
    #pragma unroll
    for (int mt = 0; mt < 4; mt++) {
        #pragma unroll
        for (int nt = 0; nt < 4; nt++) {
            int r = row0 + wm + mt*16 + g;
            int c = col0 + wn + nt*8 + tq*2;
            float b0 = bias[c], b1 = bias[c+1];
            #pragma unroll
            for (int h = 0; h < 2; h++) {
                int rr = r + h*8;
                float v0 = acc[mt][nt][h*2+0] + b0;
                float v1 = acc[mt][nt][h*2+1] + b1;
                if (MODE == 1) {
                    v0 = (v0 > 0.f) ? v0 : expm1f(v0);
                    v1 = (v1 > 0.f) ? v1 : expm1f(v1);
                }
                if (MODE == 2) {
                    const float2 rv = *(const float2*)&res[(size_t)rr*N + c];
                    v0 += rv.x; v1 += rv.y;
                }
                *(float2*)&C[(size_t)rr*N + c] = make_float2(v0, v1);
            }
        }
    }
}

// ---------------- KV[d,e] = sum_n K[n,d] V[n,e] ; Ksum[d] = sum_n K[n,d] --
__global__ __launch_bounds__(256) void kv_ksum_k(
    const float* __restrict__ Km, const float* __restrict__ Vm,
    float* __restrict__ KVg, float* __restrict__ Ksumg)
{
    __shared__ __align__(16) float Ks[16][64];
    __shared__ __align__(16) float Vs[16][64];
    int tid = threadIdx.x;
    int bh  = blockIdx.y;
    int b   = bh >> 4, h = bh & 15;
    int rbase = b*SEQ + blockIdx.x * 512;
    int cbase = h*HDIM;
    int td = tid >> 4, te = tid & 15;
    int lrow = tid >> 4;
    int lcol = (tid & 15) * 4;

    float acc[4][4] = {};
    float myk = 0.f;

    for (int t = 0; t < 512; t += 16) {
        *(float4*)&Ks[lrow][lcol] =
            *(const float4*)&Km[(size_t)(rbase + t + lrow)*DMODEL + cbase + lcol];
        *(float4*)&Vs[lrow][lcol] =
            *(const float4*)&Vm[(size_t)(rbase + t + lrow)*DMODEL + cbase + lcol];
        __syncthreads();

        #pragma unroll
        for (int kk = 0; kk < 16; kk++) {
            float kd[4], ve[4];
            #pragma unroll
            for (int i = 0; i < 4; i++) kd[i] = Ks[kk][td*4 + i];
            #pragma unroll
            for (int j = 0; j < 4; j++) ve[j] = Vs[kk][te*4 + j];
            #pragma unroll
            for (int i = 0; i < 4; i++)
                #pragma unroll
                for (int j = 0; j < 4; j++)
                    acc[i][j] += kd[i] * ve[j];
        }
        if (tid < 64) {
            #pragma unroll
            for (int kk = 0; kk < 16; kk++) myk += Ks[kk][tid];
        }
        __syncthreads();
    }

    float* KVb = KVg + (size_t)bh*HDIM*HDIM;
    #pragma unroll
    for (int i = 0; i < 4; i++)
        #pragma unroll
        for (int j = 0; j < 4; j++)
            atomicAdd(&KVb[(td*4 + i)*HDIM + te*4 + j], acc[i][j]);
    if (tid < 64) atomicAdd(&Ksumg[bh*HDIM + tid], myk);
}

// ---------------- out[n,e] = z[n] * sum_d Q[n,d] KV[d,e],  z=1/(Q.Ksum) ---
__global__ __launch_bounds__(256) void qattn_k(
    const float* __restrict__ Qm, const float* __restrict__ KVg,
    const float* __restrict__ Ksumg, float* __restrict__ attn)
{
    __shared__ float Qs[64][65];
    __shared__ __align__(16) float KVs[64][64];
    __shared__ float Ksums[64];
    __shared__ float zs[64];

    int tid = threadIdx.x;
    int bh  = blockIdx.y;
    int b   = bh >> 4, h = bh & 15;
    int rbase = b*SEQ + blockIdx.x * 64;
    int cbase = h*HDIM;

    int qrow = tid >> 2;
    int qc0  = (tid & 3) * 16;
    #pragma unroll
    for (int c = 0; c < 16; c += 4) {
        float4 v = *(const float4*)&Qm[(size_t)(rbase + qrow)*DMODEL + cbase + qc0 + c];
        Qs[qrow][qc0+c+0] = v.x;  Qs[qrow][qc0+c+1] = v.y;
        Qs[qrow][qc0+c+2] = v.z;  Qs[qrow][qc0+c+3] = v.w;
    }
    const float* KVb = KVg + (size_t)bh*HDIM*HDIM;
    #pragma unroll
    for (int c = 0; c < 16; c += 4)
        *(float4*)&KVs[qrow][qc0 + c] = *(const float4*)&KVb[qrow*64 + qc0 + c];
    if (tid < 64) Ksums[tid] = Ksumg[bh*HDIM + tid];
    __syncthreads();

    if (tid < 64) {
        float s = 0.f;
        #pragma unroll
        for (int d = 0; d < 64; d++) s += Qs[tid][d] * Ksums[d];
        zs[tid] = 1.f / s;
    }
    __syncthreads();

    int td = tid >> 4, te = tid & 15;
    float acc[4][4] = {};
    #pragma unroll
    for (int d = 0; d < 64; d++) {
        float q[4], kv[4];
        #pragma unroll
        for (int i = 0; i < 4; i++) q[i]  = Qs[td*4 + i][d];
        #pragma unroll
        for (int j = 0; j < 4; j++) kv[j] = KVs[d][te*4 + j];
        #pragma unroll
        for (int i = 0; i < 4; i++)
            #pragma unroll
            for (int j = 0; j < 4; j++)
                acc[i][j] += q[i] * kv[j];
    }
    #pragma unroll
    for (int i = 0; i < 4; i++) {
        int r = td*4 + i;
        float z = zs[r];
        #pragma unroll
        for (int j = 0; j < 4; j++)
            attn[(size_t)(rbase + r)*DMODEL + cbase + te*4 + j] = acc[i][j] * z;
    }
}

// ---------------- LayerNorm over D=1024 ------------------------------------
__global__ __launch_bounds__(256) void ln_k(
    const float* __restrict__ Y, const float* __restrict__ gamma,
    const float* __restrict__ beta, float* __restrict__ out)
{
    int row = blockIdx.x;
    int tid = threadIdx.x;
    float4 v = *(const float4*)&Y[(size_t)row*DMODEL + tid*4];
    float s  = v.x + v.y + v.z + v.w;
    float sq = v.x*v.x + v.y*v.y + v.z*v.z + v.w*v.w;
    #pragma unroll
    for (int o = 16; o > 0; o >>= 1) {
        s  += __shfl_xor_sync(0xFFFFFFFFu, s,  o);
        sq += __shfl_xor_sync(0xFFFFFFFFu, sq, o);
    }
    __shared__ float ss[8], ssq[8];
    int w = tid >> 5, l = tid & 31;
    if (l == 0) { ss[w] = s; ssq[w] = sq; }
    __syncthreads();
    if (tid == 0) {
        float S = 0.f, SQ = 0.f;
        #pragma unroll
        for (int i = 0; i < 8; i++) { S += ss[i]; SQ += ssq[i]; }
        ss[0] = S; ssq[0] = SQ;
    }
    __syncthreads();
    float mu  = ss[0] * (1.f/1024.f);
    float var = ssq[0] * (1.f/1024.f) - mu*mu;
    float inv = rsqrtf(var + 1e-3f);
    float4 gm = *(const float4*)&gamma[tid*4];
    float4 be = *(const float4*)&beta[tid*4];
    float4 o;
    o.x = (v.x - mu)*inv*gm.x + be.x;
    o.y = (v.y - mu)*inv*gm.y + be.y;
    o.z = (v.z - mu)*inv*gm.z + be.z;
    o.w = (v.w - mu)*inv*gm.w + be.w;
    *(float4*)&out[(size_t)row*DMODEL + tid*4] = o;
}

// ---------------- host entry ------------------------------------------------
extern "C" void kernel_launch(void* const* d_in, const int* in_sizes, int n_in,
                              void* d_out, int out_size)
{
    const float* x     = (const float*)d_in[0];
    const float* Wq    = (const float*)d_in[1];
    const float* bq    = (const float*)d_in[2];
    const float* Wk    = (const float*)d_in[3];
    const float* bk    = (const float*)d_in[4];
    const float* Wv    = (const float*)d_in[5];
    const float* bv    = (const float*)d_in[6];
    const float* Wo    = (const float*)d_in[7];
    const float* bo    = (const float*)d_in[8];
    const float* gamma = (const float*)d_in[9];
    const float* beta  = (const float*)d_in[10];
    float* out = (float*)d_out;

    float *Q, *K, *V, *KV, *Ksum;
    __nv_bfloat16 *Ah, *Al, *WTh, *WTl;
    cudaGetSymbolAddress((void**)&Q,    g_Q);
    cudaGetSymbolAddress((void**)&K,    g_K);
    cudaGetSymbolAddress((void**)&V,    g_V);
    cudaGetSymbolAddress((void**)&KV,   g_KV);
    cudaGetSymbolAddress((void**)&Ksum, g_Ksum);
    cudaGetSymbolAddress((void**)&Ah,   g_Ah);
    cudaGetSymbolAddress((void**)&Al,   g_Al);
    cudaGetSymbolAddress((void**)&WTh,  g_WTh);
    cudaGetSymbolAddress((void**)&WTl,  g_WTl);

    cudaFuncSetAttribute(gemm_bs<0>, cudaFuncAttributeMaxDynamicSharedMemorySize, GSMEM);
    cudaFuncSetAttribute(gemm_bs<1>, cudaFuncAttributeMaxDynamicSharedMemorySize, GSMEM);
    cudaFuncSetAttribute(gemm_bs<2>, cudaFuncAttributeMaxDynamicSharedMemorySize, GSMEM);

    float* attn = V;   // V dead after kv_ksum_k
    float* Y    = K;   // K dead after kv_ksum_k
    const size_t WSZ = (size_t)DMODEL*DMODEL;

    dim3 gg(DMODEL/BN, MTOT/BM);     // (8, 128)
    dim3 tb(32, 8);
    dim3 tg(DMODEL/32, DMODEL/32);   // (32, 32)
    const int N4 = MTOT*DMODEL/4;

    zero_k<<<(BH*HDIM*HDIM + 255)/256, 256>>>(KV, Ksum);
    split_rm<<<2048, 256>>>(x, Ah, Al, N4);
    split_tr<<<tg, tb>>>(Wq, WTh + 0*WSZ, WTl + 0*WSZ);
    split_tr<<<tg, tb>>>(Wk, WTh + 1*WSZ, WTl + 1*WSZ);
    split_tr<<<tg, tb>>>(Wv, WTh + 2*WSZ, WTl + 2*WSZ);
    split_tr<<<tg, tb>>>(Wo, WTh + 3*WSZ, WTl + 3*WSZ);

    gemm_bs<1><<<gg, 256, GSMEM>>>(Ah, Al, WTh + 0*WSZ, WTl + 0*WSZ, bq, nullptr, Q);
    gemm_bs<1><<<gg, 256, GSMEM>>>(Ah, Al, WTh + 1*WSZ, WTl + 1*WSZ, bk, nullptr, K);
    gemm_bs<0><<<gg, 256, GSMEM>>>(Ah, Al, WTh + 2*WSZ, WTl + 2*WSZ, bv, nullptr, V);

    kv_ksum_k<<<dim3(8, BH), 256>>>(K, V, KV, Ksum);
    qattn_k<<<dim3(SEQ/64, BH), 256>>>(Q, KV, Ksum, attn);

    split_rm<<<2048, 256>>>(attn, Ah, Al, N4);   // reuse split buffers
    gemm_bs<2><<<gg, 256, GSMEM>>>(Ah, Al, WTh + 3*WSZ, WTl + 3*WSZ, bo, x, Y);

    ln_k<<<MTOT, 256>>>(Y, gamma, beta, out);
}

// round 7
// speedup vs baseline: 2.4673x; 1.0404x over previous
#include <cuda_runtime.h>
#include <cuda_bf16.h>
#include <math.h>
#include <stdint.h>

#define MTOT   16384      // B*N = 4*4096
#define DMODEL 1024
#define NHEADS 16
#define HDIM   64
#define BATCH  4
#define SEQ    4096
#define BH     (BATCH*NHEADS)   // 64

// ---------------- scratch (device globals: allocation-free) ----------------
__device__ float g_Q[(size_t)MTOT*DMODEL];
__device__ float g_K[(size_t)MTOT*DMODEL];
__device__ float g_V[(size_t)MTOT*DMODEL];
__device__ float g_KV[BH*HDIM*HDIM];
__device__ float g_Ksum[BH*HDIM];
__device__ __nv_bfloat16 g_Ah[(size_t)MTOT*DMODEL];
__device__ __nv_bfloat16 g_Al[(size_t)MTOT*DMODEL];
__device__ __nv_bfloat16 g_WTh[4ULL*DMODEL*DMODEL];   // [w][n][k]
__device__ __nv_bfloat16 g_WTl[4ULL*DMODEL*DMODEL];

__device__ __forceinline__ void split2(float x, __nv_bfloat16& h, __nv_bfloat16& l) {
    h = __float2bfloat16_rn(x);
    l = __float2bfloat16_rn(x - __bfloat162float(h));
}

// ---------------- zero KV/Ksum ---------------------------------------------
__global__ void zero_k(float* __restrict__ KV, float* __restrict__ Ksum) {
    int i = blockIdx.x * blockDim.x + threadIdx.x;
    if (i < BH*HDIM*HDIM) KV[i] = 0.f;
    if (i < BH*HDIM)      Ksum[i] = 0.f;
}

// ---------------- split fp32 row-major -> bf16 hi/lo -----------------------
__global__ __launch_bounds__(256) void split_rm(
    const float* __restrict__ in, __nv_bfloat16* __restrict__ H,
    __nv_bfloat16* __restrict__ L, int n4)
{
    for (int i = blockIdx.x*blockDim.x + threadIdx.x; i < n4; i += gridDim.x*blockDim.x) {
        float4 v = ((const float4*)in)[i];
        __nv_bfloat16 h0,h1,h2,h3,l0,l1,l2,l3;
        split2(v.x,h0,l0); split2(v.y,h1,l1); split2(v.z,h2,l2); split2(v.w,h3,l3);
        __nv_bfloat162* Hp = (__nv_bfloat162*)H;
        __nv_bfloat162* Lp = (__nv_bfloat162*)L;
        Hp[i*2+0] = __nv_bfloat162{h0,h1}; Hp[i*2+1] = __nv_bfloat162{h2,h3};
        Lp[i*2+0] = __nv_bfloat162{l0,l1}; Lp[i*2+1] = __nv_bfloat162{l2,l3};
    }
}

// ---------------- split + transpose (4 weights in one launch) --------------
__global__ __launch_bounds__(256) void split_tr4(
    const float* __restrict__ W0, const float* __restrict__ W1,
    const float* __restrict__ W2, const float* __restrict__ W3,
    __nv_bfloat16* __restrict__ Th, __nv_bfloat16* __restrict__ Tl)
{
    __shared__ float tile[32][33];
    int tx = threadIdx.x, ty = threadIdx.y;            // (32, 8)
    int k0 = blockIdx.y * 32, n0 = blockIdx.x * 32;
    int wz = blockIdx.z;
    const float* W = (wz == 0) ? W0 : (wz == 1) ? W1 : (wz == 2) ? W2 : W3;
    const size_t WSZ = (size_t)DMODEL*DMODEL;
    #pragma unroll
    for (int i = 0; i < 32; i += 8)
        tile[ty+i][tx] = W[(size_t)(k0+ty+i)*DMODEL + n0 + tx];
    __syncthreads();
    #pragma unroll
    for (int i = 0; i < 32; i += 8) {
        float v = tile[tx][ty+i];
        __nv_bfloat16 h, l; split2(v, h, l);
        size_t o = wz*WSZ + (size_t)(n0+ty+i)*DMODEL + k0 + tx;
        Th[o] = h; Tl[o] = l;
    }
}

// ---------------- bf16-split tensor-core GEMM core -------------------------
#define BM 128
#define BN 128
#define BK 32
#define PIT 40                       // elems: 80B pitch -> conflict-free ldmatrix
#define STG_B (BM*PIT*2)             // 10240 bytes per stage per buffer
#define BUF_B (2*STG_B)              // 20480 bytes per buffer (2 stages)
#define GSMEM (4*BUF_B)              // 81920 total dynamic smem

__device__ __forceinline__ uint32_t s2u(const void* p) {
    uint32_t a;
    asm("{ .reg .u64 t; cvta.to.shared.u64 t, %1; cvt.u32.u64 %0, t; }"
        : "=r"(a) : "l"(p));
    return a;
}
__device__ __forceinline__ void cp16(uint32_t dst, const void* src) {
    asm volatile("cp.async.cg.shared.global [%0], [%1], 16;\n" :: "r"(dst), "l"(src));
}
__device__ __forceinline__ void cp_commit() { asm volatile("cp.async.commit_group;\n"); }
template<int N> __device__ __forceinline__ void cp_wait() {
    asm volatile("cp.async.wait_group %0;\n" :: "n"(N));
}
__device__ __forceinline__ void ldm_x4(uint32_t r[4], uint32_t addr) {
    asm volatile("ldmatrix.sync.aligned.m8n8.x4.shared.b16 {%0,%1,%2,%3}, [%4];"
        : "=r"(r[0]), "=r"(r[1]), "=r"(r[2]), "=r"(r[3]) : "r"(addr));
}
__device__ __forceinline__ void mma_bf16(float c[4],
    uint32_t a0, uint32_t a1, uint32_t a2, uint32_t a3, uint32_t b0, uint32_t b1) {
    asm volatile(
        "mma.sync.aligned.m16n8k16.row.col.f32.bf16.bf16.f32 "
        "{%0,%1,%2,%3}, {%4,%5,%6,%7}, {%8,%9}, {%0,%1,%2,%3};"
        : "+f"(c[0]), "+f"(c[1]), "+f"(c[2]), "+f"(c[3])
        : "r"(a0), "r"(a1), "r"(a2), "r"(a3), "r"(b0), "r"(b1));
}

// Mainloop shared by both GEMM kernels; leaves results in acc.
struct GemmCtx {
    uint32_t bAh, bAl, bBh, bBl;
    uint32_t aoffA, aoffB;
    int r0c, c0c, r1c, c1c;
    const __nv_bfloat16 *AhR, *AlR, *BhR, *BlR;
};

__device__ __forceinline__ void gemm_mainloop(GemmCtx& cx, float acc[4][4][4]) {
    const int K = DMODEL;
    auto issue = [&](int st, int k0) {
        uint32_t d0 = (uint32_t)(st*STG_B + cx.r0c*(PIT*2) + cx.c0c*16);
        uint32_t d1 = (uint32_t)(st*STG_B + cx.r1c*(PIT*2) + cx.c1c*16);
        size_t g0 = (size_t)cx.r0c*K + k0 + cx.c0c*8;
        size_t g1 = (size_t)cx.r1c*K + k0 + cx.c1c*8;
        cp16(cx.bAh + d0, cx.AhR + g0);  cp16(cx.bAh + d1, cx.AhR + g1);
        cp16(cx.bAl + d0, cx.AlR + g0);  cp16(cx.bAl + d1, cx.AlR + g1);
        cp16(cx.bBh + d0, cx.BhR + g0);  cp16(cx.bBh + d1, cx.BhR + g1);
        cp16(cx.bBl + d0, cx.BlR + g0);  cp16(cx.bBl + d1, cx.BlR + g1);
        cp_commit();
    };

    const int NITER = K / BK;   // 32
    issue(0, 0);
    issue(1, BK);

    for (int it = 0; it < NITER; it++) {
        int st = it & 1;
        if (it + 2 < NITER) cp_wait<1>(); else cp_wait<0>();
        __syncthreads();

        uint32_t sA = st * STG_B;
        #pragma unroll
        for (int ks = 0; ks < 2; ks++) {
            uint32_t kso = ks * 32;             // 16 elems = 32B
            uint32_t af[4][4], bh[8], bl[8];
            #pragma unroll
            for (int p = 0; p < 2; p++) {
                ldm_x4(&bh[p*4], cx.bBh + sA + cx.aoffB + p*(16*PIT*2) + kso);
                ldm_x4(&bl[p*4], cx.bBl + sA + cx.aoffB + p*(16*PIT*2) + kso);
            }
            #pragma unroll
            for (int mt = 0; mt < 4; mt++)
                ldm_x4(af[mt], cx.bAh + sA + cx.aoffA + mt*(16*PIT*2) + kso);
            #pragma unroll
            for (int mt = 0; mt < 4; mt++)
                #pragma unroll
                for (int nt = 0; nt < 4; nt++) {
                    mma_bf16(acc[mt][nt], af[mt][0],af[mt][1],af[mt][2],af[mt][3],
                             bh[nt*2], bh[nt*2+1]);
                    mma_bf16(acc[mt][nt], af[mt][0],af[mt][1],af[mt][2],af[mt][3],
                             bl[nt*2], bl[nt*2+1]);
                }
            #pragma unroll
            for (int mt = 0; mt < 4; mt++)
                ldm_x4(af[mt], cx.bAl + sA + cx.aoffA + mt*(16*PIT*2) + kso);
            #pragma unroll
            for (int mt = 0; mt < 4; mt++)
                #pragma unroll
                for (int nt = 0; nt < 4; nt++)
                    mma_bf16(acc[mt][nt], af[mt][0],af[mt][1],af[mt][2],af[mt][3],
                             bh[nt*2], bh[nt*2+1]);
        }
        __syncthreads();
        if (it + 2 < NITER) issue(st, (it+2)*BK);
    }
}

__device__ __forceinline__ void gemm_ctx_init(GemmCtx& cx, uint32_t sb,
    int row0, int col0, int tid,
    const __nv_bfloat16* Ahg, const __nv_bfloat16* Alg,
    const __nv_bfloat16* BTh, const __nv_bfloat16* BTl)
{
    cx.bAh = sb + 0*BUF_B;  cx.bAl = sb + 1*BUF_B;
    cx.bBh = sb + 2*BUF_B;  cx.bBl = sb + 3*BUF_B;
    int w = tid >> 5, lane = tid & 31;
    int wm = (w & 1) * 64, wn = (w >> 1) * 32;
    cx.aoffA = (uint32_t)(((wm + (lane & 15)) * PIT + (lane >> 4) * 8) * 2);
    cx.aoffB = (uint32_t)(((wn + (lane & 7) + (lane >> 4) * 8) * PIT +
                           ((lane >> 3) & 1) * 8) * 2);
    int ch0 = tid, ch1 = tid + 256;
    cx.r0c = ch0 >> 2; cx.c0c = ch0 & 3;
    cx.r1c = ch1 >> 2; cx.c1c = ch1 & 3;
    cx.AhR = Ahg + (size_t)row0 * DMODEL;
    cx.AlR = Alg + (size_t)row0 * DMODEL;
    cx.BhR = BTh + (size_t)col0 * DMODEL;
    cx.BlR = BTl + (size_t)col0 * DMODEL;
}

// ---------------- merged Q/K/V GEMM (grid.z selects weight) ----------------
__global__ __launch_bounds__(256, 2) void gemm_qkv(
    const __nv_bfloat16* __restrict__ Ahg, const __nv_bfloat16* __restrict__ Alg,
    const __nv_bfloat16* __restrict__ WTh, const __nv_bfloat16* __restrict__ WTl,
    const float* __restrict__ bq, const float* __restrict__ bk,
    const float* __restrict__ bv,
    float* __restrict__ Q, float* __restrict__ K, float* __restrict__ V)
{
    extern __shared__ __align__(16) char smem[];
    int tid  = threadIdx.x;
    int row0 = blockIdx.y * BM;
    int col0 = blockIdx.x * BN;
    int wz   = blockIdx.z;
    const size_t WSZ = (size_t)DMODEL*DMODEL;
    const float* bias = (wz == 0) ? bq : (wz == 1) ? bk : bv;
    float* C = (wz == 0) ? Q : (wz == 1) ? K : V;
    bool elu = (wz < 2);

    GemmCtx cx;
    gemm_ctx_init(cx, s2u(smem), row0, col0, tid,
                  Ahg, Alg, WTh + wz*WSZ, WTl + wz*WSZ);

    float acc[4][4][4];
    #pragma unroll
    for (int i = 0; i < 4; i++)
        #pragma unroll
        for (int j = 0; j < 4; j++)
            #pragma unroll
            for (int e = 0; e < 4; e++) acc[i][j][e] = 0.f;

    gemm_mainloop(cx, acc);

    int w = tid >> 5, lane = tid & 31;
    int wm = (w & 1) * 64, wn = (w >> 1) * 32;
    int g = lane >> 2, tq = lane & 3;
    #pragma unroll
    for (int mt = 0; mt < 4; mt++) {
        #pragma unroll
        for (int nt = 0; nt < 4; nt++) {
            int r = row0 + wm + mt*16 + g;
            int c = col0 + wn + nt*8 + tq*2;
            float b0 = bias[c], b1 = bias[c+1];
            #pragma unroll
            for (int h = 0; h < 2; h++) {
                int rr = r + h*8;
                float v0 = acc[mt][nt][h*2+0] + b0;
                float v1 = acc[mt][nt][h*2+1] + b1;
                if (elu) {
                    v0 = (v0 > 0.f) ? v0 : expm1f(v0);
                    v1 = (v1 > 0.f) ? v1 : expm1f(v1);
                }
                *(float2*)&C[(size_t)rr*DMODEL + c] = make_float2(v0, v1);
            }
        }
    }
}

// ---------------- final GEMM: Y = x + attn @ Wo + bo -----------------------
__global__ __launch_bounds__(256, 2) void gemm_out(
    const __nv_bfloat16* __restrict__ Ahg, const __nv_bfloat16* __restrict__ Alg,
    const __nv_bfloat16* __restrict__ BTh, const __nv_bfloat16* __restrict__ BTl,
    const float* __restrict__ bias, const float* __restrict__ res,
    float* __restrict__ C)
{
    extern __shared__ __align__(16) char smem[];
    int tid  = threadIdx.x;
    int row0 = blockIdx.y * BM;
    int col0 = blockIdx.x * BN;

    GemmCtx cx;
    gemm_ctx_init(cx, s2u(smem), row0, col0, tid, Ahg, Alg, BTh, BTl);

    float acc[4][4][4];
    #pragma unroll
    for (int i = 0; i < 4; i++)
        #pragma unroll
        for (int j = 0; j < 4; j++)
            #pragma unroll
            for (int e = 0; e < 4; e++) acc[i][j][e] = 0.f;

    gemm_mainloop(cx, acc);

    int w = tid >> 5, lane = tid & 31;
    int wm = (w & 1) * 64, wn = (w >> 1) * 32;
    int g = lane >> 2, tq = lane & 3;
    #pragma unroll
    for (int mt = 0; mt < 4; mt++) {
        #pragma unroll
        for (int nt = 0; nt < 4; nt++) {
            int r = row0 + wm + mt*16 + g;
            int c = col0 + wn + nt*8 + tq*2;
            float b0 = bias[c], b1 = bias[c+1];
            #pragma unroll
            for (int h = 0; h < 2; h++) {
                int rr = r + h*8;
                const float2 rv = *(const float2*)&res[(size_t)rr*DMODEL + c];
                float v0 = acc[mt][nt][h*2+0] + b0 + rv.x;
                float v1 = acc[mt][nt][h*2+1] + b1 + rv.y;
                *(float2*)&C[(size_t)rr*DMODEL + c] = make_float2(v0, v1);
            }
        }
    }
}

// ---------------- KV[d,e] = sum_n K[n,d] V[n,e] ; Ksum[d] = sum_n K[n,d] --
__global__ __launch_bounds__(256) void kv_ksum_k(
    const float* __restrict__ Km, const float* __restrict__ Vm,
    float* __restrict__ KVg, float* __restrict__ Ksumg)
{
    __shared__ __align__(16) float Ks[16][64];
    __shared__ __align__(16) float Vs[16][64];
    int tid = threadIdx.x;
    int bh  = blockIdx.y;
    int b   = bh >> 4, h = bh & 15;
    int rbase = b*SEQ + blockIdx.x * 512;
    int cbase = h*HDIM;
    int td = tid >> 4, te = tid & 15;
    int lrow = tid >> 4;
    int lcol = (tid & 15) * 4;

    float acc[4][4] = {};
    float myk = 0.f;

    for (int t = 0; t < 512; t += 16) {
        *(float4*)&Ks[lrow][lcol] =
            *(const float4*)&Km[(size_t)(rbase + t + lrow)*DMODEL + cbase + lcol];
        *(float4*)&Vs[lrow][lcol] =
            *(const float4*)&Vm[(size_t)(rbase + t + lrow)*DMODEL + cbase + lcol];
        __syncthreads();

        #pragma unroll
        for (int kk = 0; kk < 16; kk++) {
            float kd[4], ve[4];
            #pragma unroll
            for (int i = 0; i < 4; i++) kd[i] = Ks[kk][td*4 + i];
            #pragma unroll
            for (int j = 0; j < 4; j++) ve[j] = Vs[kk][te*4 + j];
            #pragma unroll
            for (int i = 0; i < 4; i++)
                #pragma unroll
                for (int j = 0; j < 4; j++)
                    acc[i][j] += kd[i] * ve[j];
        }
        if (tid < 64) {
            #pragma unroll
            for (int kk = 0; kk < 16; kk++) myk += Ks[kk][tid];
        }
        __syncthreads();
    }

    float* KVb = KVg + (size_t)bh*HDIM*HDIM;
    #pragma unroll
    for (int i = 0; i < 4; i++)
        #pragma unroll
        for (int j = 0; j < 4; j++)
            atomicAdd(&KVb[(td*4 + i)*HDIM + te*4 + j], acc[i][j]);
    if (tid < 64) atomicAdd(&Ksumg[bh*HDIM + tid], myk);
}

// ---------------- qattn: out = z * (Q @ KV), fused bf16 split epilogue -----
__global__ __launch_bounds__(256) void qattn_k(
    const float* __restrict__ Qm, const float* __restrict__ KVg,
    const float* __restrict__ Ksumg,
    __nv_bfloat16* __restrict__ AttH, __nv_bfloat16* __restrict__ AttL)
{
    __shared__ float Qs[64][65];
    __shared__ __align__(16) float KVs[64][64];
    __shared__ float Ksums[64];
    __shared__ float zs[64];

    int tid = threadIdx.x;
    int bh  = blockIdx.y;
    int b   = bh >> 4, h = bh & 15;
    int rbase = b*SEQ + blockIdx.x * 64;
    int cbase = h*HDIM;

    int qrow = tid >> 2;
    int qc0  = (tid & 3) * 16;
    #pragma unroll
    for (int c = 0; c < 16; c += 4) {
        float4 v = *(const float4*)&Qm[(size_t)(rbase + qrow)*DMODEL + cbase + qc0 + c];
        Qs[qrow][qc0+c+0] = v.x;  Qs[qrow][qc0+c+1] = v.y;
        Qs[qrow][qc0+c+2] = v.z;  Qs[qrow][qc0+c+3] = v.w;
    }
    const float* KVb = KVg + (size_t)bh*HDIM*HDIM;
    #pragma unroll
    for (int c = 0; c < 16; c += 4)
        *(float4*)&KVs[qrow][qc0 + c] = *(const float4*)&KVb[qrow*64 + qc0 + c];
    if (tid < 64) Ksums[tid] = Ksumg[bh*HDIM + tid];
    __syncthreads();

    if (tid < 64) {
        float s = 0.f;
        #pragma unroll
        for (int d = 0; d < 64; d++) s += Qs[tid][d] * Ksums[d];
        zs[tid] = 1.f / s;
    }
    __syncthreads();

    int td = tid >> 4, te = tid & 15;
    float acc[4][4] = {};
    #pragma unroll
    for (int d = 0; d < 64; d++) {
        float q[4], kv[4];
        #pragma unroll
        for (int i = 0; i < 4; i++) q[i]  = Qs[td*4 + i][d];
        #pragma unroll
        for (int j = 0; j < 4; j++) kv[j] = KVs[d][te*4 + j];
        #pragma unroll
        for (int i = 0; i < 4; i++)
            #pragma unroll
            for (int j = 0; j < 4; j++)
                acc[i][j] += q[i] * kv[j];
    }
    #pragma unroll
    for (int i = 0; i < 4; i++) {
        int r = td*4 + i;
        float z = zs[r];
        __nv_bfloat16 hh[4], ll[4];
        #pragma unroll
        for (int j = 0; j < 4; j++) split2(acc[i][j] * z, hh[j], ll[j]);
        size_t o = ((size_t)(rbase + r)*DMODEL + cbase + te*4) >> 1;
        ((__nv_bfloat162*)AttH)[o+0] = __nv_bfloat162{hh[0], hh[1]};
        ((__nv_bfloat162*)AttH)[o+1] = __nv_bfloat162{hh[2], hh[3]};
        ((__nv_bfloat162*)AttL)[o+0] = __nv_bfloat162{ll[0], ll[1]};
        ((__nv_bfloat162*)AttL)[o+1] = __nv_bfloat162{ll[2], ll[3]};
    }
}

// ---------------- LayerNorm over D=1024 ------------------------------------
__global__ __launch_bounds__(256) void ln_k(
    const float* __restrict__ Y, const float* __restrict__ gamma,
    const float* __restrict__ beta, float* __restrict__ out)
{
    int row = blockIdx.x;
    int tid = threadIdx.x;
    float4 v = *(const float4*)&Y[(size_t)row*DMODEL + tid*4];
    float s  = v.x + v.y + v.z + v.w;
    float sq = v.x*v.x + v.y*v.y + v.z*v.z + v.w*v.w;
    #pragma unroll
    for (int o = 16; o > 0; o >>= 1) {
        s  += __shfl_xor_sync(0xFFFFFFFFu, s,  o);
        sq += __shfl_xor_sync(0xFFFFFFFFu, sq, o);
    }
    __shared__ float ss[8], ssq[8];
    int w = tid >> 5, l = tid & 31;
    if (l == 0) { ss[w] = s; ssq[w] = sq; }
    __syncthreads();
    if (tid == 0) {
        float S = 0.f, SQ = 0.f;
        #pragma unroll
        for (int i = 0; i < 8; i++) { S += ss[i]; SQ += ssq[i]; }
        ss[0] = S; ssq[0] = SQ;
    }
    __syncthreads();
    float mu  = ss[0] * (1.f/1024.f);
    float var = ssq[0] * (1.f/1024.f) - mu*mu;
    float inv = rsqrtf(var + 1e-3f);
    float4 gm = *(const float4*)&gamma[tid*4];
    float4 be = *(const float4*)&beta[tid*4];
    float4 o;
    o.x = (v.x - mu)*inv*gm.x + be.x;
    o.y = (v.y - mu)*inv*gm.y + be.y;
    o.z = (v.z - mu)*inv*gm.z + be.z;
    o.w = (v.w - mu)*inv*gm.w + be.w;
    *(float4*)&out[(size_t)row*DMODEL + tid*4] = o;
}

// ---------------- host entry ------------------------------------------------
extern "C" void kernel_launch(void* const* d_in, const int* in_sizes, int n_in,
                              void* d_out, int out_size)
{
    const float* x     = (const float*)d_in[0];
    const float* Wq    = (const float*)d_in[1];
    const float* bq    = (const float*)d_in[2];
    const float* Wk    = (const float*)d_in[3];
    const float* bk    = (const float*)d_in[4];
    const float* Wv    = (const float*)d_in[5];
    const float* bv    = (const float*)d_in[6];
    const float* Wo    = (const float*)d_in[7];
    const float* bo    = (const float*)d_in[8];
    const float* gamma = (const float*)d_in[9];
    const float* beta  = (const float*)d_in[10];
    float* out = (float*)d_out;

    float *Q, *K, *V, *KV, *Ksum;
    __nv_bfloat16 *Ah, *Al, *WTh, *WTl;
    cudaGetSymbolAddress((void**)&Q,    g_Q);
    cudaGetSymbolAddress((void**)&K,    g_K);
    cudaGetSymbolAddress((void**)&V,    g_V);
    cudaGetSymbolAddress((void**)&KV,   g_KV);
    cudaGetSymbolAddress((void**)&Ksum, g_Ksum);
    cudaGetSymbolAddress((void**)&Ah,   g_Ah);
    cudaGetSymbolAddress((void**)&Al,   g_Al);
    cudaGetSymbolAddress((void**)&WTh,  g_WTh);
    cudaGetSymbolAddress((void**)&WTl,  g_WTl);

    cudaFuncSetAttribute(gemm_qkv, cudaFuncAttributeMaxDynamicSharedMemorySize, GSMEM);
    cudaFuncSetAttribute(gemm_out, cudaFuncAttributeMaxDynamicSharedMemorySize, GSMEM);

    float* Y = K;   // K dead after kv_ksum_k
    const size_t WSZ = (size_t)DMODEL*DMODEL;

    dim3 gqkv(DMODEL/BN, MTOT/BM, 3);   // (8, 128, 3)
    dim3 gout(DMODEL/BN, MTOT/BM);      // (8, 128)
    dim3 tb(32, 8);
    dim3 tg4(DMODEL/32, DMODEL/32, 4);  // (32, 32, 4)
    const int N4 = MTOT*DMODEL/4;

    zero_k<<<(BH*HDIM*HDIM + 255)/256, 256>>>(KV, Ksum);
    split_rm<<<2048, 256>>>(x, Ah, Al, N4);
    split_tr4<<<tg4, tb>>>(Wq, Wk, Wv, Wo, WTh, WTl);

    gemm_qkv<<<gqkv, 256, GSMEM>>>(Ah, Al, WTh, WTl, bq, bk, bv, Q, K, V);

    kv_ksum_k<<<dim3(8, BH), 256>>>(K, V, KV, Ksum);
    qattn_k<<<dim3(SEQ/64, BH), 256>>>(Q, KV, Ksum, Ah, Al);  // split fused

    gemm_out<<<gout, 256, GSMEM>>>(Ah, Al, WTh + 3*WSZ, WTl + 3*WSZ, bo, x, Y);

    ln_k<<<MTOT, 256>>>(Y, gamma, beta, out);
}

// round 10
// speedup vs baseline: 2.8168x; 1.1416x over previous
#include <cuda_runtime.h>
#include <cuda_bf16.h>
#include <math.h>
#include <stdint.h>

#define MTOT   16384      // B*N = 4*4096
#define DMODEL 1024
#define NHEADS 16
#define HDIM   64
#define BATCH  4
#define SEQ    4096
#define BH     (BATCH*NHEADS)   // 64

// ---------------- scratch (device globals: allocation-free) ----------------
__device__ float g_Q[(size_t)MTOT*DMODEL];
__device__ float g_K[(size_t)MTOT*DMODEL];
__device__ float g_V[(size_t)MTOT*DMODEL];
__device__ float g_KV[BH*HDIM*HDIM];
__device__ float g_Ksum[BH*HDIM];
__device__ __nv_bfloat16 g_Ah[(size_t)MTOT*DMODEL];
__device__ __nv_bfloat16 g_Al[(size_t)MTOT*DMODEL];
__device__ __nv_bfloat16 g_WTh[4ULL*DMODEL*DMODEL];   // [w][n][k]
__device__ __nv_bfloat16 g_WTl[4ULL*DMODEL*DMODEL];

__device__ __forceinline__ void split2(float x, __nv_bfloat16& h, __nv_bfloat16& l) {
    h = __float2bfloat16_rn(x);
    l = __float2bfloat16_rn(x - __bfloat162float(h));
}

// ---------------- zero KV/Ksum ---------------------------------------------
__global__ void zero_k(float* __restrict__ KV, float* __restrict__ Ksum) {
    int i = blockIdx.x * blockDim.x + threadIdx.x;
    if (i < BH*HDIM*HDIM) KV[i] = 0.f;
    if (i < BH*HDIM)      Ksum[i] = 0.f;
}

// ---------------- split fp32 row-major -> bf16 hi/lo -----------------------
__global__ __launch_bounds__(256) void split_rm(
    const float* __restrict__ in, __nv_bfloat16* __restrict__ H,
    __nv_bfloat16* __restrict__ L, int n4)
{
    for (int i = blockIdx.x*blockDim.x + threadIdx.x; i < n4; i += gridDim.x*blockDim.x) {
        float4 v = ((const float4*)in)[i];
        __nv_bfloat16 h0,h1,h2,h3,l0,l1,l2,l3;
        split2(v.x,h0,l0); split2(v.y,h1,l1); split2(v.z,h2,l2); split2(v.w,h3,l3);
        __nv_bfloat162* Hp = (__nv_bfloat162*)H;
        __nv_bfloat162* Lp = (__nv_bfloat162*)L;
        Hp[i*2+0] = __nv_bfloat162{h0,h1}; Hp[i*2+1] = __nv_bfloat162{h2,h3};
        Lp[i*2+0] = __nv_bfloat162{l0,l1}; Lp[i*2+1] = __nv_bfloat162{l2,l3};
    }
}

// ---------------- split + transpose (4 weights in one launch) --------------
__global__ __launch_bounds__(256) void split_tr4(
    const float* __restrict__ W0, const float* __restrict__ W1,
    const float* __restrict__ W2, const float* __restrict__ W3,
    __nv_bfloat16* __restrict__ Th, __nv_bfloat16* __restrict__ Tl)
{
    __shared__ float tile[32][33];
    int tx = threadIdx.x, ty = threadIdx.y;            // (32, 8)
    int k0 = blockIdx.y * 32, n0 = blockIdx.x * 32;
    int wz = blockIdx.z;
    const float* W = (wz == 0) ? W0 : (wz == 1) ? W1 : (wz == 2) ? W2 : W3;
    const size_t WSZ = (size_t)DMODEL*DMODEL;
    #pragma unroll
    for (int i = 0; i < 32; i += 8)
        tile[ty+i][tx] = W[(size_t)(k0+ty+i)*DMODEL + n0 + tx];
    __syncthreads();
    #pragma unroll
    for (int i = 0; i < 32; i += 8) {
        float v = tile[tx][ty+i];
        __nv_bfloat16 h, l; split2(v, h, l);
        size_t o = wz*WSZ + (size_t)(n0+ty+i)*DMODEL + k0 + tx;
        Th[o] = h; Tl[o] = l;
    }
}

// ---------------- bf16-split tensor-core GEMM core -------------------------
// 128x128 tile, BK=32, 3-stage swizzled smem, 1 barrier/iter.
#define BM 128
#define BN 128
#define BK 32
#define STG 8192                     // bytes per stage per buffer (128 rows x 64B)
#define NSTAGE 3
#define BUFSZ (NSTAGE*STG)           // 24576
#define GSMEM (4*BUFSZ)              // 98304

__device__ __forceinline__ uint32_t s2u(const void* p) {
    uint32_t a;
    asm("{ .reg .u64 t; cvta.to.shared.u64 t, %1; cvt.u32.u64 %0, t; }"
        : "=r"(a) : "l"(p));
    return a;
}
__device__ __forceinline__ void cp16(uint32_t dst, const void* src) {
    asm volatile("cp.async.cg.shared.global [%0], [%1], 16;\n" :: "r"(dst), "l"(src));
}
__device__ __forceinline__ void cp_commit() { asm volatile("cp.async.commit_group;\n"); }
template<int N> __device__ __forceinline__ void cp_wait() {
    asm volatile("cp.async.wait_group %0;\n" :: "n"(N));
}
__device__ __forceinline__ void ldm_x4(uint32_t r[4], uint32_t addr) {
    asm volatile("ldmatrix.sync.aligned.m8n8.x4.shared.b16 {%0,%1,%2,%3}, [%4];"
        : "=r"(r[0]), "=r"(r[1]), "=r"(r[2]), "=r"(r[3]) : "r"(addr));
}
__device__ __forceinline__ void mma_bf16(float c[4],
    uint32_t a0, uint32_t a1, uint32_t a2, uint32_t a3, uint32_t b0, uint32_t b1) {
    asm volatile(
        "mma.sync.aligned.m16n8k16.row.col.f32.bf16.bf16.f32 "
        "{%0,%1,%2,%3}, {%4,%5,%6,%7}, {%8,%9}, {%0,%1,%2,%3};"
        : "+f"(c[0]), "+f"(c[1]), "+f"(c[2]), "+f"(c[3])
        : "r"(a0), "r"(a1), "r"(a2), "r"(a3), "r"(b0), "r"(b1));
}
// SW64-style swizzle on 64B rows: XOR chunk bits [4:5] with row bits [1:2]
__device__ __forceinline__ uint32_t sw64(uint32_t off) {
    return off ^ ((off >> 3) & 0x30);
}

struct GemmCtx {
    uint32_t bAh, bAl, bBh, bBl;
    uint32_t aoffA, aoffB;           // swizzle-folded lane bases (linear bit5 = 0)
    uint32_t d0sw, d1sw;             // cp.async dest offsets (swizzled)
    const __nv_bfloat16 *AhR, *AlR, *BhR, *BlR;
    size_t g0, g1;                   // gmem element offsets (minus k0)
};

__device__ __forceinline__ void gemm_ctx_init(GemmCtx& cx, uint32_t sb,
    int row0, int col0, int tid,
    const __nv_bfloat16* Ahg, const __nv_bfloat16* Alg,
    const __nv_bfloat16* BTh, const __nv_bfloat16* BTl)
{
    cx.bAh = sb + 0*BUFSZ;  cx.bAl = sb + 1*BUFSZ;
    cx.bBh = sb + 2*BUFSZ;  cx.bBl = sb + 3*BUFSZ;
    int w = tid >> 5, lane = tid & 31;
    int wm = (w & 1) * 64, wn = (w >> 1) * 32;
    // A fragment lane base: row = wm + (lane&15), chunk = (lane>>4) (16B units)
    uint32_t linA = (uint32_t)((wm + (lane & 15)) * 64 + (lane >> 4) * 16);
    cx.aoffA = sw64(linA);   // linear bit5 == 0: compose k-step via XOR 32
    // B fragment lane base: row = wn + (lane&7) + (lane>>4)*8, chunk = (lane>>3)&1
    uint32_t linB = (uint32_t)((wn + (lane & 7) + ((lane >> 4) << 3)) * 64 +
                               ((lane >> 3) & 1) * 16);
    cx.aoffB = sw64(linB);
    // cp.async: 512 chunks of 16B per buffer-stage; 2 per thread
    int r0 = tid >> 2,          c0 = tid & 3;
    int r1 = (tid + 256) >> 2,  c1 = (tid + 256) & 3;
    cx.d0sw = sw64((uint32_t)(r0*64 + c0*16));
    cx.d1sw = sw64((uint32_t)(r1*64 + c1*16));
    cx.g0 = (size_t)r0*DMODEL + c0*8;
    cx.g1 = (size_t)r1*DMODEL + c1*8;
    cx.AhR = Ahg + (size_t)row0 * DMODEL;
    cx.AlR = Alg + (size_t)row0 * DMODEL;
    cx.BhR = BTh + (size_t)col0 * DMODEL;
    cx.BlR = BTl + (size_t)col0 * DMODEL;
}

__device__ __forceinline__ void gemm_issue(GemmCtx& cx, int st, int k0) {
    uint32_t s = (uint32_t)st * STG;
    cp16(cx.bAh + s + cx.d0sw, cx.AhR + cx.g0 + k0);
    cp16(cx.bAh + s + cx.d1sw, cx.AhR + cx.g1 + k0);
    cp16(cx.bAl + s + cx.d0sw, cx.AlR + cx.g0 + k0);
    cp16(cx.bAl + s + cx.d1sw, cx.AlR + cx.g1 + k0);
    cp16(cx.bBh + s + cx.d0sw, cx.BhR + cx.g0 + k0);
    cp16(cx.bBh + s + cx.d1sw, cx.BhR + cx.g1 + k0);
    cp16(cx.bBl + s + cx.d0sw, cx.BlR + cx.g0 + k0);
    cp16(cx.bBl + s + cx.d1sw, cx.BlR + cx.g1 + k0);
    cp_commit();
}

__device__ __forceinline__ void gemm_mainloop(GemmCtx& cx, float acc[4][4][4]) {
    const int NITER = DMODEL / BK;   // 32
    gemm_issue(cx, 0, 0);
    gemm_issue(cx, 1, BK);

    int st = 0;
    for (int it = 0; it < NITER; it++) {
        if (it == NITER-1) cp_wait<0>(); else cp_wait<1>();
        __syncthreads();
        if (it + 2 < NITER) {
            int st2 = st + 2; if (st2 >= 3) st2 -= 3;
            gemm_issue(cx, st2, (it+2)*BK);
        }

        uint32_t sA = (uint32_t)st * STG;
        #pragma unroll
        for (int ks = 0; ks < 2; ks++) {
            uint32_t kso = ks * 32;             // 16 elems = 32B; compose via XOR
            uint32_t aA = cx.aoffA ^ kso;       // valid: linear base bit5 == 0
            uint32_t aB = cx.aoffB ^ kso;
            uint32_t af[4][4], bh[8], bl[8];
            #pragma unroll
            for (int p = 0; p < 2; p++) {
                ldm_x4(&bh[p*4], cx.bBh + sA + aB + p*1024);
                ldm_x4(&bl[p*4], cx.bBl + sA + aB + p*1024);
            }
            #pragma unroll
            for (int mt = 0; mt < 4; mt++)
                ldm_x4(af[mt], cx.bAh + sA + aA + mt*1024);
            #pragma unroll
            for (int mt = 0; mt < 4; mt++)
                #pragma unroll
                for (int nt = 0; nt < 4; nt++) {
                    mma_bf16(acc[mt][nt], af[mt][0],af[mt][1],af[mt][2],af[mt][3],
                             bh[nt*2], bh[nt*2+1]);
                    mma_bf16(acc[mt][nt], af[mt][0],af[mt][1],af[mt][2],af[mt][3],
                             bl[nt*2], bl[nt*2+1]);
                }
            #pragma unroll
            for (int mt = 0; mt < 4; mt++)
                ldm_x4(af[mt], cx.bAl + sA + aA + mt*1024);
            #pragma unroll
            for (int mt = 0; mt < 4; mt++)
                #pragma unroll
                for (int nt = 0; nt < 4; nt++)
                    mma_bf16(acc[mt][nt], af[mt][0],af[mt][1],af[mt][2],af[mt][3],
                             bh[nt*2], bh[nt*2+1]);
        }
        if (++st >= 3) st = 0;
    }
}

// ---------------- merged Q/K/V GEMM (grid.z selects weight) ----------------
__global__ __launch_bounds__(256, 2) void gemm_qkv(
    const __nv_bfloat16* __restrict__ Ahg, const __nv_bfloat16* __restrict__ Alg,
    const __nv_bfloat16* __restrict__ WTh, const __nv_bfloat16* __restrict__ WTl,
    const float* __restrict__ bq, const float* __restrict__ bk,
    const float* __restrict__ bv,
    float* __restrict__ Q, float* __restrict__ K, float* __restrict__ V)
{
    extern __shared__ __align__(1024) char smem[];
    int tid  = threadIdx.x;
    int row0 = blockIdx.y * BM;
    int col0 = blockIdx.x * BN;
    int wz   = blockIdx.z;
    const size_t WSZ = (size_t)DMODEL*DMODEL;
    const float* bias = (wz == 0) ? bq : (wz == 1) ? bk : bv;
    float* C = (wz == 0) ? Q : (wz == 1) ? K : V;
    bool elu = (wz < 2);

    GemmCtx cx;
    gemm_ctx_init(cx, s2u(smem), row0, col0, tid,
                  Ahg, Alg, WTh + wz*WSZ, WTl + wz*WSZ);

    float acc[4][4][4];
    #pragma unroll
    for (int i = 0; i < 4; i++)
        #pragma unroll
        for (int j = 0; j < 4; j++)
            #pragma unroll
            for (int e = 0; e < 4; e++) acc[i][j][e] = 0.f;

    gemm_mainloop(cx, acc);

    int w = tid >> 5, lane = tid & 31;
    int wm = (w & 1) * 64, wn = (w >> 1) * 32;
    int g = lane >> 2, tq = lane & 3;
    #pragma unroll
    for (int mt = 0; mt < 4; mt++) {
        #pragma unroll
        for (int nt = 0; nt < 4; nt++) {
            int r = row0 + wm + mt*16 + g;
            int c = col0 + wn + nt*8 + tq*2;
            float b0 = bias[c], b1 = bias[c+1];
            #pragma unroll
            for (int h = 0; h < 2; h++) {
                int rr = r + h*8;
                float v0 = acc[mt][nt][h*2+0] + b0;
                float v1 = acc[mt][nt][h*2+1] + b1;
                if (elu) {
                    v0 = (v0 > 0.f) ? v0 : expm1f(v0);
                    v1 = (v1 > 0.f) ? v1 : expm1f(v1);
                }
                *(float2*)&C[(size_t)rr*DMODEL + c] = make_float2(v0, v1);
            }
        }
    }
}

// ---------------- final GEMM: Y = x + attn @ Wo + bo -----------------------
__global__ __launch_bounds__(256, 2) void gemm_out(
    const __nv_bfloat16* __restrict__ Ahg, const __nv_bfloat16* __restrict__ Alg,
    const __nv_bfloat16* __restrict__ BTh, const __nv_bfloat16* __restrict__ BTl,
    const float* __restrict__ bias, const float* __restrict__ res,
    float* __restrict__ C)
{
    extern __shared__ __align__(1024) char smem[];
    int tid  = threadIdx.x;
    int row0 = blockIdx.y * BM;
    int col0 = blockIdx.x * BN;

    GemmCtx cx;
    gemm_ctx_init(cx, s2u(smem), row0, col0, tid, Ahg, Alg, BTh, BTl);

    float acc[4][4][4];
    #pragma unroll
    for (int i = 0; i < 4; i++)
        #pragma unroll
        for (int j = 0; j < 4; j++)
            #pragma unroll
            for (int e = 0; e < 4; e++) acc[i][j][e] = 0.f;

    gemm_mainloop(cx, acc);

    int w = tid >> 5, lane = tid & 31;
    int wm = (w & 1) * 64, wn = (w >> 1) * 32;
    int g = lane >> 2, tq = lane & 3;
    #pragma unroll
    for (int mt = 0; mt < 4; mt++) {
        #pragma unroll
        for (int nt = 0; nt < 4; nt++) {
            int r = row0 + wm + mt*16 + g;
            int c = col0 + wn + nt*8 + tq*2;
            float b0 = bias[c], b1 = bias[c+1];
            #pragma unroll
            for (int h = 0; h < 2; h++) {
                int rr = r + h*8;
                const float2 rv = *(const float2*)&res[(size_t)rr*DMODEL + c];
                float v0 = acc[mt][nt][h*2+0] + b0 + rv.x;
                float v1 = acc[mt][nt][h*2+1] + b1 + rv.y;
                *(float2*)&C[(size_t)rr*DMODEL + c] = make_float2(v0, v1);
            }
        }
    }
}

// ---------------- KV[d,e] = sum_n K[n,d] V[n,e] ; Ksum[d] = sum_n K[n,d] --
__global__ __launch_bounds__(256) void kv_ksum_k(
    const float* __restrict__ Km, const float* __restrict__ Vm,
    float* __restrict__ KVg, float* __restrict__ Ksumg)
{
    __shared__ __align__(16) float Ks[16][64];
    __shared__ __align__(16) float Vs[16][64];
    int tid = threadIdx.x;
    int bh  = blockIdx.y;
    int b   = bh >> 4, h = bh & 15;
    int rbase = b*SEQ + blockIdx.x * 512;
    int cbase = h*HDIM;
    int td = tid >> 4, te = tid & 15;
    int lrow = tid >> 4;
    int lcol = (tid & 15) * 4;

    float acc[4][4] = {};
    float myk = 0.f;

    for (int t = 0; t < 512; t += 16) {
        *(float4*)&Ks[lrow][lcol] =
            *(const float4*)&Km[(size_t)(rbase + t + lrow)*DMODEL + cbase + lcol];
        *(float4*)&Vs[lrow][lcol] =
            *(const float4*)&Vm[(size_t)(rbase + t + lrow)*DMODEL + cbase + lcol];
        __syncthreads();

        #pragma unroll
        for (int kk = 0; kk < 16; kk++) {
            float kd[4], ve[4];
            #pragma unroll
            for (int i = 0; i < 4; i++) kd[i] = Ks[kk][td*4 + i];
            #pragma unroll
            for (int j = 0; j < 4; j++) ve[j] = Vs[kk][te*4 + j];
            #pragma unroll
            for (int i = 0; i < 4; i++)
                #pragma unroll
                for (int j = 0; j < 4; j++)
                    acc[i][j] += kd[i] * ve[j];
        }
        if (tid < 64) {
            #pragma unroll
            for (int kk = 0; kk < 16; kk++) myk += Ks[kk][tid];
        }
        __syncthreads();
    }

    float* KVb = KVg + (size_t)bh*HDIM*HDIM;
    #pragma unroll
    for (int i = 0; i < 4; i++)
        #pragma unroll
        for (int j = 0; j < 4; j++)
            atomicAdd(&KVb[(td*4 + i)*HDIM + te*4 + j], acc[i][j]);
    if (tid < 64) atomicAdd(&Ksumg[bh*HDIM + tid], myk);
}

// ---------------- qattn: out = z * (Q @ KV), fused bf16 split epilogue -----
__global__ __launch_bounds__(256) void qattn_k(
    const float* __restrict__ Qm, const float* __restrict__ KVg,
    const float* __restrict__ Ksumg,
    __nv_bfloat16* __restrict__ AttH, __nv_bfloat16* __restrict__ AttL)
{
    __shared__ float Qs[64][65];
    __shared__ __align__(16) float KVs[64][64];
    __shared__ float Ksums[64];
    __shared__ float zs[64];

    int tid = threadIdx.x;
    int bh  = blockIdx.y;
    int b   = bh >> 4, h = bh & 15;
    int rbase = b*SEQ + blockIdx.x * 64;
    int cbase = h*HDIM;

    int qrow = tid >> 2;
    int qc0  = (tid & 3) * 16;
    #pragma unroll
    for (int c = 0; c < 16; c += 4) {
        float4 v = *(const float4*)&Qm[(size_t)(rbase + qrow)*DMODEL + cbase + qc0 + c];
        Qs[qrow][qc0+c+0] = v.x;  Qs[qrow][qc0+c+1] = v.y;
        Qs[qrow][qc0+c+2] = v.z;  Qs[qrow][qc0+c+3] = v.w;
    }
    const float* KVb = KVg + (size_t)bh*HDIM*HDIM;
    #pragma unroll
    for (int c = 0; c < 16; c += 4)
        *(float4*)&KVs[qrow][qc0 + c] = *(const float4*)&KVb[qrow*64 + qc0 + c];
    if (tid < 64) Ksums[tid] = Ksumg[bh*HDIM + tid];
    __syncthreads();

    if (tid < 64) {
        float s = 0.f;
        #pragma unroll
        for (int d = 0; d < 64; d++) s += Qs[tid][d] * Ksums[d];
        zs[tid] = 1.f / s;
    }
    __syncthreads();

    int td = tid >> 4, te = tid & 15;
    float acc[4][4] = {};
    #pragma unroll
    for (int d = 0; d < 64; d++) {
        float q[4], kv[4];
        #pragma unroll
        for (int i = 0; i < 4; i++) q[i]  = Qs[td*4 + i][d];
        #pragma unroll
        for (int j = 0; j < 4; j++) kv[j] = KVs[d][te*4 + j];
        #pragma unroll
        for (int i = 0; i < 4; i++)
            #pragma unroll
            for (int j = 0; j < 4; j++)
                acc[i][j] += q[i] * kv[j];
    }
    #pragma unroll
    for (int i = 0; i < 4; i++) {
        int r = td*4 + i;
        float z = zs[r];
        __nv_bfloat16 hh[4], ll[4];
        #pragma unroll
        for (int j = 0; j < 4; j++) split2(acc[i][j] * z, hh[j], ll[j]);
        size_t o = ((size_t)(rbase + r)*DMODEL + cbase + te*4) >> 1;
        ((__nv_bfloat162*)AttH)[o+0] = __nv_bfloat162{hh[0], hh[1]};
        ((__nv_bfloat162*)AttH)[o+1] = __nv_bfloat162{hh[2], hh[3]};
        ((__nv_bfloat162*)AttL)[o+0] = __nv_bfloat162{ll[0], ll[1]};
        ((__nv_bfloat162*)AttL)[o+1] = __nv_bfloat162{ll[2], ll[3]};
    }
}

// ---------------- LayerNorm over D=1024 ------------------------------------
__global__ __launch_bounds__(256) void ln_k(
    const float* __restrict__ Y, const float* __restrict__ gamma,
    const float* __restrict__ beta, float* __restrict__ out)
{
    int row = blockIdx.x;
    int tid = threadIdx.x;
    float4 v = *(const float4*)&Y[(size_t)row*DMODEL + tid*4];
    float s  = v.x + v.y + v.z + v.w;
    float sq = v.x*v.x + v.y*v.y + v.z*v.z + v.w*v.w;
    #pragma unroll
    for (int o = 16; o > 0; o >>= 1) {
        s  += __shfl_xor_sync(0xFFFFFFFFu, s,  o);
        sq += __shfl_xor_sync(0xFFFFFFFFu, sq, o);
    }
    __shared__ float ss[8], ssq[8];
    int w = tid >> 5, l = tid & 31;
    if (l == 0) { ss[w] = s; ssq[w] = sq; }
    __syncthreads();
    if (tid == 0) {
        float S = 0.f, SQ = 0.f;
        #pragma unroll
        for (int i = 0; i < 8; i++) { S += ss[i]; SQ += ssq[i]; }
        ss[0] = S; ssq[0] = SQ;
    }
    __syncthreads();
    float mu  = ss[0] * (1.f/1024.f);
    float var = ssq[0] * (1.f/1024.f) - mu*mu;
    float inv = rsqrtf(var + 1e-3f);
    float4 gm = *(const float4*)&gamma[tid*4];
    float4 be = *(const float4*)&beta[tid*4];
    float4 o;
    o.x = (v.x - mu)*inv*gm.x + be.x;
    o.y = (v.y - mu)*inv*gm.y + be.y;
    o.z = (v.z - mu)*inv*gm.z + be.z;
    o.w = (v.w - mu)*inv*gm.w + be.w;
    *(float4*)&out[(size_t)row*DMODEL + tid*4] = o;
}

// ---------------- host entry ------------------------------------------------
extern "C" void kernel_launch(void* const* d_in, const int* in_sizes, int n_in,
                              void* d_out, int out_size)
{
    const float* x     = (const float*)d_in[0];
    const float* Wq    = (const float*)d_in[1];
    const float* bq    = (const float*)d_in[2];
    const float* Wk    = (const float*)d_in[3];
    const float* bk    = (const float*)d_in[4];
    const float* Wv    = (const float*)d_in[5];
    const float* bv    = (const float*)d_in[6];
    const float* Wo    = (const float*)d_in[7];
    const float* bo    = (const float*)d_in[8];
    const float* gamma = (const float*)d_in[9];
    const float* beta  = (const float*)d_in[10];
    float* out = (float*)d_out;

    float *Q, *K, *V, *KV, *Ksum;
    __nv_bfloat16 *Ah, *Al, *WTh, *WTl;
    cudaGetSymbolAddress((void**)&Q,    g_Q);
    cudaGetSymbolAddress((void**)&K,    g_K);
    cudaGetSymbolAddress((void**)&V,    g_V);
    cudaGetSymbolAddress((void**)&KV,   g_KV);
    cudaGetSymbolAddress((void**)&Ksum, g_Ksum);
    cudaGetSymbolAddress((void**)&Ah,   g_Ah);
    cudaGetSymbolAddress((void**)&Al,   g_Al);
    cudaGetSymbolAddress((void**)&WTh,  g_WTh);
    cudaGetSymbolAddress((void**)&WTl,  g_WTl);

    cudaFuncSetAttribute(gemm_qkv, cudaFuncAttributeMaxDynamicSharedMemorySize, GSMEM);
    cudaFuncSetAttribute(gemm_out, cudaFuncAttributeMaxDynamicSharedMemorySize, GSMEM);

    float* Y = K;   // K dead after kv_ksum_k
    const size_t WSZ = (size_t)DMODEL*DMODEL;

    dim3 gqkv(DMODEL/BN, MTOT/BM, 3);   // (8, 128, 3)
    dim3 gout(DMODEL/BN, MTOT/BM);      // (8, 128)
    dim3 tb(32, 8);
    dim3 tg4(DMODEL/32, DMODEL/32, 4);  // (32, 32, 4)
    const int N4 = MTOT*DMODEL/4;

    zero_k<<<(BH*HDIM*HDIM + 255)/256, 256>>>(KV, Ksum);
    split_rm<<<2048, 256>>>(x, Ah, Al, N4);
    split_tr4<<<tg4, tb>>>(Wq, Wk, Wv, Wo, WTh, WTl);

    gemm_qkv<<<gqkv, 256, GSMEM>>>(Ah, Al, WTh, WTl, bq, bk, bv, Q, K, V);

    kv_ksum_k<<<dim3(8, BH), 256>>>(K, V, KV, Ksum);
    qattn_k<<<dim3(SEQ/64, BH), 256>>>(Q, KV, Ksum, Ah, Al);  // split fused

    gemm_out<<<gout, 256, GSMEM>>>(Ah, Al, WTh + 3*WSZ, WTl + 3*WSZ, bo, x, Y);

    ln_k<<<MTOT, 256>>>(Y, gamma, beta, out);
}

// round 11
// speedup vs baseline: 2.8707x; 1.0191x over previous
#include <cuda_runtime.h>
#include <cuda_bf16.h>
#include <math.h>
#include <stdint.h>

#define MTOT   16384      // B*N = 4*4096
#define DMODEL 1024
#define NHEADS 16
#define HDIM   64
#define BATCH  4
#define SEQ    4096
#define BH     (BATCH*NHEADS)   // 64

// ---------------- scratch (device globals: allocation-free) ----------------
__device__ float g_Y[(size_t)MTOT*DMODEL];
__device__ __nv_bfloat16 g_Ah[(size_t)MTOT*DMODEL];
__device__ __nv_bfloat16 g_Al[(size_t)MTOT*DMODEL];
__device__ __nv_bfloat16 g_Qh[(size_t)MTOT*DMODEL];
__device__ __nv_bfloat16 g_Ql[(size_t)MTOT*DMODEL];
__device__ __nv_bfloat16 g_Kh[(size_t)MTOT*DMODEL];
__device__ __nv_bfloat16 g_Kl[(size_t)MTOT*DMODEL];
__device__ __nv_bfloat16 g_Vh[(size_t)MTOT*DMODEL];
__device__ __nv_bfloat16 g_Vl[(size_t)MTOT*DMODEL];
__device__ __nv_bfloat16 g_WTh[4ULL*DMODEL*DMODEL];   // [w][n][k]
__device__ __nv_bfloat16 g_WTl[4ULL*DMODEL*DMODEL];
__device__ __nv_bfloat16 g_KVTh[BH*HDIM*HDIM];        // [bh][e][d]
__device__ __nv_bfloat16 g_KVTl[BH*HDIM*HDIM];
__device__ float g_Ksum[BH*HDIM];

__device__ __forceinline__ void split2(float x, __nv_bfloat16& h, __nv_bfloat16& l) {
    h = __float2bfloat16_rn(x);
    l = __float2bfloat16_rn(x - __bfloat162float(h));
}
__device__ __forceinline__ uint32_t pack2(__nv_bfloat16 a, __nv_bfloat16 b) {
    __nv_bfloat162 t{a, b};
    return *(uint32_t*)&t;
}

// ---------------- PTX helpers ----------------------------------------------
__device__ __forceinline__ uint32_t s2u(const void* p) {
    uint32_t a;
    asm("{ .reg .u64 t; cvta.to.shared.u64 t, %1; cvt.u32.u64 %0, t; }"
        : "=r"(a) : "l"(p));
    return a;
}
__device__ __forceinline__ void cp16(uint32_t dst, const void* src) {
    asm volatile("cp.async.cg.shared.global [%0], [%1], 16;\n" :: "r"(dst), "l"(src));
}
__device__ __forceinline__ void cp_commit() { asm volatile("cp.async.commit_group;\n"); }
template<int N> __device__ __forceinline__ void cp_wait() {
    asm volatile("cp.async.wait_group %0;\n" :: "n"(N));
}
__device__ __forceinline__ void ldm_x4(uint32_t r[4], uint32_t addr) {
    asm volatile("ldmatrix.sync.aligned.m8n8.x4.shared.b16 {%0,%1,%2,%3}, [%4];"
        : "=r"(r[0]), "=r"(r[1]), "=r"(r[2]), "=r"(r[3]) : "r"(addr));
}
__device__ __forceinline__ void ldm_x4t(uint32_t r[4], uint32_t addr) {
    asm volatile("ldmatrix.sync.aligned.m8n8.x4.trans.shared.b16 {%0,%1,%2,%3}, [%4];"
        : "=r"(r[0]), "=r"(r[1]), "=r"(r[2]), "=r"(r[3]) : "r"(addr));
}
__device__ __forceinline__ void mma_bf16(float c[4],
    uint32_t a0, uint32_t a1, uint32_t a2, uint32_t a3, uint32_t b0, uint32_t b1) {
    asm volatile(
        "mma.sync.aligned.m16n8k16.row.col.f32.bf16.bf16.f32 "
        "{%0,%1,%2,%3}, {%4,%5,%6,%7}, {%8,%9}, {%0,%1,%2,%3};"
        : "+f"(c[0]), "+f"(c[1]), "+f"(c[2]), "+f"(c[3])
        : "r"(a0), "r"(a1), "r"(a2), "r"(a3), "r"(b0), "r"(b1));
}
__device__ __forceinline__ uint32_t sw64(uint32_t off) {
    return off ^ ((off >> 3) & 0x30);
}

// ---------------- split fp32 row-major -> bf16 hi/lo -----------------------
__global__ __launch_bounds__(256) void split_rm(
    const float* __restrict__ in, __nv_bfloat16* __restrict__ H,
    __nv_bfloat16* __restrict__ L, int n4)
{
    for (int i = blockIdx.x*blockDim.x + threadIdx.x; i < n4; i += gridDim.x*blockDim.x) {
        float4 v = ((const float4*)in)[i];
        __nv_bfloat16 h0,h1,h2,h3,l0,l1,l2,l3;
        split2(v.x,h0,l0); split2(v.y,h1,l1); split2(v.z,h2,l2); split2(v.w,h3,l3);
        __nv_bfloat162* Hp = (__nv_bfloat162*)H;
        __nv_bfloat162* Lp = (__nv_bfloat162*)L;
        Hp[i*2+0] = __nv_bfloat162{h0,h1}; Hp[i*2+1] = __nv_bfloat162{h2,h3};
        Lp[i*2+0] = __nv_bfloat162{l0,l1}; Lp[i*2+1] = __nv_bfloat162{l2,l3};
    }
}

// ---------------- split + transpose (4 weights in one launch) --------------
__global__ __launch_bounds__(256) void split_tr4(
    const float* __restrict__ W0, const float* __restrict__ W1,
    const float* __restrict__ W2, const float* __restrict__ W3,
    __nv_bfloat16* __restrict__ Th, __nv_bfloat16* __restrict__ Tl)
{
    __shared__ float tile[32][33];
    int tx = threadIdx.x, ty = threadIdx.y;            // (32, 8)
    int k0 = blockIdx.y * 32, n0 = blockIdx.x * 32;
    int wz = blockIdx.z;
    const float* W = (wz == 0) ? W0 : (wz == 1) ? W1 : (wz == 2) ? W2 : W3;
    const size_t WSZ = (size_t)DMODEL*DMODEL;
    #pragma unroll
    for (int i = 0; i < 32; i += 8)
        tile[ty+i][tx] = W[(size_t)(k0+ty+i)*DMODEL + n0 + tx];
    __syncthreads();
    #pragma unroll
    for (int i = 0; i < 32; i += 8) {
        float v = tile[tx][ty+i];
        __nv_bfloat16 h, l; split2(v, h, l);
        size_t o = wz*WSZ + (size_t)(n0+ty+i)*DMODEL + k0 + tx;
        Th[o] = h; Tl[o] = l;
    }
}

// ---------------- bf16-split dense GEMM core (3-stage, swizzled) -----------
#define BM 128
#define BN 128
#define BK 32
#define STG 8192
#define NSTAGE 3
#define BUFSZ (NSTAGE*STG)
#define GSMEM (4*BUFSZ)              // 98304

struct GemmCtx {
    uint32_t bAh, bAl, bBh, bBl;
    uint32_t aoffA, aoffB;
    uint32_t d0sw, d1sw;
    const __nv_bfloat16 *AhR, *AlR, *BhR, *BlR;
    size_t g0, g1;
};

__device__ __forceinline__ void gemm_ctx_init(GemmCtx& cx, uint32_t sb,
    int row0, int col0, int tid,
    const __nv_bfloat16* Ahg, const __nv_bfloat16* Alg,
    const __nv_bfloat16* BTh, const __nv_bfloat16* BTl)
{
    cx.bAh = sb + 0*BUFSZ;  cx.bAl = sb + 1*BUFSZ;
    cx.bBh = sb + 2*BUFSZ;  cx.bBl = sb + 3*BUFSZ;
    int w = tid >> 5, lane = tid & 31;
    int wm = (w & 1) * 64, wn = (w >> 1) * 32;
    uint32_t linA = (uint32_t)((wm + (lane & 15)) * 64 + (lane >> 4) * 16);
    cx.aoffA = sw64(linA);
    uint32_t linB = (uint32_t)((wn + (lane & 7) + ((lane >> 4) << 3)) * 64 +
                               ((lane >> 3) & 1) * 16);
    cx.aoffB = sw64(linB);
    int r0 = tid >> 2,          c0 = tid & 3;
    int r1 = (tid + 256) >> 2,  c1 = (tid + 256) & 3;
    cx.d0sw = sw64((uint32_t)(r0*64 + c0*16));
    cx.d1sw = sw64((uint32_t)(r1*64 + c1*16));
    cx.g0 = (size_t)r0*DMODEL + c0*8;
    cx.g1 = (size_t)r1*DMODEL + c1*8;
    cx.AhR = Ahg + (size_t)row0 * DMODEL;
    cx.AlR = Alg + (size_t)row0 * DMODEL;
    cx.BhR = BTh + (size_t)col0 * DMODEL;
    cx.BlR = BTl + (size_t)col0 * DMODEL;
}

__device__ __forceinline__ void gemm_issue(GemmCtx& cx, int st, int k0) {
    uint32_t s = (uint32_t)st * STG;
    cp16(cx.bAh + s + cx.d0sw, cx.AhR + cx.g0 + k0);
    cp16(cx.bAh + s + cx.d1sw, cx.AhR + cx.g1 + k0);
    cp16(cx.bAl + s + cx.d0sw, cx.AlR + cx.g0 + k0);
    cp16(cx.bAl + s + cx.d1sw, cx.AlR + cx.g1 + k0);
    cp16(cx.bBh + s + cx.d0sw, cx.BhR + cx.g0 + k0);
    cp16(cx.bBh + s + cx.d1sw, cx.BhR + cx.g1 + k0);
    cp16(cx.bBl + s + cx.d0sw, cx.BlR + cx.g0 + k0);
    cp16(cx.bBl + s + cx.d1sw, cx.BlR + cx.g1 + k0);
    cp_commit();
}

__device__ __forceinline__ void gemm_mainloop(GemmCtx& cx, float acc[4][4][4]) {
    const int NITER = DMODEL / BK;   // 32
    gemm_issue(cx, 0, 0);
    gemm_issue(cx, 1, BK);

    int st = 0;
    for (int it = 0; it < NITER; it++) {
        if (it == NITER-1) cp_wait<0>(); else cp_wait<1>();
        __syncthreads();
        if (it + 2 < NITER) {
            int st2 = st + 2; if (st2 >= 3) st2 -= 3;
            gemm_issue(cx, st2, (it+2)*BK);
        }

        uint32_t sA = (uint32_t)st * STG;
        #pragma unroll
        for (int ks = 0; ks < 2; ks++) {
            uint32_t kso = ks * 32;
            uint32_t aA = cx.aoffA ^ kso;
            uint32_t aB = cx.aoffB ^ kso;
            uint32_t af[4][4], bh[8], bl[8];
            #pragma unroll
            for (int p = 0; p < 2; p++) {
                ldm_x4(&bh[p*4], cx.bBh + sA + aB + p*1024);
                ldm_x4(&bl[p*4], cx.bBl + sA + aB + p*1024);
            }
            #pragma unroll
            for (int mt = 0; mt < 4; mt++)
                ldm_x4(af[mt], cx.bAh + sA + aA + mt*1024);
            #pragma unroll
            for (int mt = 0; mt < 4; mt++)
                #pragma unroll
                for (int nt = 0; nt < 4; nt++) {
                    mma_bf16(acc[mt][nt], af[mt][0],af[mt][1],af[mt][2],af[mt][3],
                             bh[nt*2], bh[nt*2+1]);
                    mma_bf16(acc[mt][nt], af[mt][0],af[mt][1],af[mt][2],af[mt][3],
                             bl[nt*2], bl[nt*2+1]);
                }
            #pragma unroll
            for (int mt = 0; mt < 4; mt++)
                ldm_x4(af[mt], cx.bAl + sA + aA + mt*1024);
            #pragma unroll
            for (int mt = 0; mt < 4; mt++)
                #pragma unroll
                for (int nt = 0; nt < 4; nt++)
                    mma_bf16(acc[mt][nt], af[mt][0],af[mt][1],af[mt][2],af[mt][3],
                             bh[nt*2], bh[nt*2+1]);
        }
        if (++st >= 3) st = 0;
    }
}

// ---------------- merged Q/K/V GEMM: writes bf16 hi/lo outputs -------------
__global__ __launch_bounds__(256, 2) void gemm_qkv(
    const __nv_bfloat16* __restrict__ Ahg, const __nv_bfloat16* __restrict__ Alg,
    const __nv_bfloat16* __restrict__ WTh, const __nv_bfloat16* __restrict__ WTl,
    const float* __restrict__ bq, const float* __restrict__ bk,
    const float* __restrict__ bv,
    __nv_bfloat16* __restrict__ Qh, __nv_bfloat16* __restrict__ Ql,
    __nv_bfloat16* __restrict__ Kh, __nv_bfloat16* __restrict__ Kl,
    __nv_bfloat16* __restrict__ Vh, __nv_bfloat16* __restrict__ Vl)
{
    extern __shared__ __align__(1024) char smem[];
    int tid  = threadIdx.x;
    int row0 = blockIdx.y * BM;
    int col0 = blockIdx.x * BN;
    int wz   = blockIdx.z;
    const size_t WSZ = (size_t)DMODEL*DMODEL;
    const float* bias = (wz == 0) ? bq : (wz == 1) ? bk : bv;
    __nv_bfloat16* H = (wz == 0) ? Qh : (wz == 1) ? Kh : Vh;
    __nv_bfloat16* L = (wz == 0) ? Ql : (wz == 1) ? Kl : Vl;
    bool elu = (wz < 2);

    GemmCtx cx;
    gemm_ctx_init(cx, s2u(smem), row0, col0, tid,
                  Ahg, Alg, WTh + wz*WSZ, WTl + wz*WSZ);

    float acc[4][4][4];
    #pragma unroll
    for (int i = 0; i < 4; i++)
        #pragma unroll
        for (int j = 0; j < 4; j++)
            #pragma unroll
            for (int e = 0; e < 4; e++) acc[i][j][e] = 0.f;

    gemm_mainloop(cx, acc);

    int w = tid >> 5, lane = tid & 31;
    int wm = (w & 1) * 64, wn = (w >> 1) * 32;
    int g = lane >> 2, tq = lane & 3;
    #pragma unroll
    for (int mt = 0; mt < 4; mt++) {
        #pragma unroll
        for (int nt = 0; nt < 4; nt++) {
            int r = row0 + wm + mt*16 + g;
            int c = col0 + wn + nt*8 + tq*2;
            float b0 = bias[c], b1 = bias[c+1];
            #pragma unroll
            for (int h = 0; h < 2; h++) {
                int rr = r + h*8;
                float v0 = acc[mt][nt][h*2+0] + b0;
                float v1 = acc[mt][nt][h*2+1] + b1;
                if (elu) {
                    v0 = (v0 > 0.f) ? v0 : expm1f(v0);
                    v1 = (v1 > 0.f) ? v1 : expm1f(v1);
                }
                __nv_bfloat16 h0,l0,h1,l1;
                split2(v0,h0,l0); split2(v1,h1,l1);
                size_t idx = (size_t)rr*DMODEL + c;
                *(uint32_t*)&H[idx] = pack2(h0,h1);
                *(uint32_t*)&L[idx] = pack2(l0,l1);
            }
        }
    }
}

// ---------------- final GEMM: Y = x + attn @ Wo + bo -----------------------
__global__ __launch_bounds__(256, 2) void gemm_out(
    const __nv_bfloat16* __restrict__ Ahg, const __nv_bfloat16* __restrict__ Alg,
    const __nv_bfloat16* __restrict__ BTh, const __nv_bfloat16* __restrict__ BTl,
    const float* __restrict__ bias, const float* __restrict__ res,
    float* __restrict__ C)
{
    extern __shared__ __align__(1024) char smem[];
    int tid  = threadIdx.x;
    int row0 = blockIdx.y * BM;
    int col0 = blockIdx.x * BN;

    GemmCtx cx;
    gemm_ctx_init(cx, s2u(smem), row0, col0, tid, Ahg, Alg, BTh, BTl);

    float acc[4][4][4];
    #pragma unroll
    for (int i = 0; i < 4; i++)
        #pragma unroll
        for (int j = 0; j < 4; j++)
            #pragma unroll
            for (int e = 0; e < 4; e++) acc[i][j][e] = 0.f;

    gemm_mainloop(cx, acc);

    int w = tid >> 5, lane = tid & 31;
    int wm = (w & 1) * 64, wn = (w >> 1) * 32;
    int g = lane >> 2, tq = lane & 3;
    #pragma unroll
    for (int mt = 0; mt < 4; mt++) {
        #pragma unroll
        for (int nt = 0; nt < 4; nt++) {
            int r = row0 + wm + mt*16 + g;
            int c = col0 + wn + nt*8 + tq*2;
            float b0 = bias[c], b1 = bias[c+1];
            #pragma unroll
            for (int h = 0; h < 2; h++) {
                int rr = r + h*8;
                const float2 rv = *(const float2*)&res[(size_t)rr*DMODEL + c];
                float v0 = acc[mt][nt][h*2+0] + b0 + rv.x;
                float v1 = acc[mt][nt][h*2+1] + b1 + rv.y;
                *(float2*)&C[(size_t)rr*DMODEL + c] = make_float2(v0, v1);
            }
        }
    }
}

// ---------------- kv_ksum_t: KVT[e][d] = (K^T V)^T, Ksum via ones-MMA ------
// One CTA per bh; 128 threads (4 warps, 2x2 of 32x32). Trans ldmatrix.
#define KVP 144                        // smem row pitch bytes (64 d x 2B + 16 pad)
#define KVT_TILE (32*KVP)              // 4608 per operand tile
#define KVT_STG  (4*KVT_TILE)          // 18432 per stage

__global__ __launch_bounds__(128) void kv_ksum_t(
    const __nv_bfloat16* __restrict__ Kh_, const __nv_bfloat16* __restrict__ Kl_,
    const __nv_bfloat16* __restrict__ Vh_, const __nv_bfloat16* __restrict__ Vl_,
    __nv_bfloat16* __restrict__ KVTh, __nv_bfloat16* __restrict__ KVTl,
    float* __restrict__ Ksumg)
{
    __shared__ __align__(16) char smem[2*KVT_STG];
    uint32_t sb = s2u(smem);
    int tid = threadIdx.x;
    int bh  = blockIdx.x;
    int b   = bh >> 4, h = bh & 15;
    int w   = tid >> 5, lane = tid & 31;
    int wm  = (w & 1) * 32, wn = (w >> 1) * 32;

    const size_t rb = (size_t)b * SEQ * DMODEL + (size_t)h * HDIM;
    const __nv_bfloat16* src[4] = {Kh_ + rb, Kl_ + rb, Vh_ + rb, Vl_ + rb};

    // trans-ldmatrix lane offsets (bytes, within stage tile)
    uint32_t arowA = (uint32_t)((lane & 7) + ((lane >> 4) & 1) * 8);   // n row
    uint32_t acolA = (uint32_t)((wm + ((lane >> 3) & 1) * 8) * 2);     // d col
    uint32_t arowB = (uint32_t)((lane & 7) + ((lane >> 3) & 1) * 8);   // n row
    uint32_t acolB = (uint32_t)((wn + ((lane >> 4) & 1) * 8) * 2);     // e col

    float acc[2][4][4] = {};
    float aks[2][4]    = {};
    const uint32_t ONES = 0x3F803F80u;

    auto issue = [&](int st, int n0) {
        #pragma unroll
        for (int i = 0; i < 8; i++) {
            int t = i >> 1;
            int r = (i & 1) * 16 + (tid >> 3);
            int c = tid & 7;
            cp16(sb + st*KVT_STG + t*KVT_TILE + r*KVP + c*16,
                 src[t] + (size_t)(n0 + r) * DMODEL + c*8);
        }
        cp_commit();
    };

    const int NS = SEQ / 32;   // 128
    issue(0, 0); issue(1, 32);
    int st = 0;
    for (int it = 0; it < NS; it++) {
        if (it == NS-1) cp_wait<0>(); else cp_wait<1>();
        __syncthreads();
        uint32_t S = sb + st*KVT_STG;
        #pragma unroll
        for (int hh = 0; hh < 2; hh++) {
            uint32_t ro = (uint32_t)hh * 16 * KVP;
            uint32_t akh[2][4], akl[2][4], bvh[2][4], bvl[2][4];
            #pragma unroll
            for (int mt = 0; mt < 2; mt++) {
                uint32_t ad = ro + arowA*KVP + acolA + mt*32;
                ldm_x4t(akh[mt], S + 0*KVT_TILE + ad);
                ldm_x4t(akl[mt], S + 1*KVT_TILE + ad);
            }
            #pragma unroll
            for (int et = 0; et < 2; et++) {
                uint32_t ad = ro + arowB*KVP + acolB + et*32;
                ldm_x4t(bvh[et], S + 2*KVT_TILE + ad);
                ldm_x4t(bvl[et], S + 3*KVT_TILE + ad);
            }
            #pragma unroll
            for (int mt = 0; mt < 2; mt++) {
                #pragma unroll
                for (int nt = 0; nt < 4; nt++) {
                    uint32_t h0 = bvh[nt>>1][(nt&1)*2], h1 = bvh[nt>>1][(nt&1)*2+1];
                    uint32_t l0 = bvl[nt>>1][(nt&1)*2], l1 = bvl[nt>>1][(nt&1)*2+1];
                    mma_bf16(acc[mt][nt], akh[mt][0],akh[mt][1],akh[mt][2],akh[mt][3], h0,h1);
                    mma_bf16(acc[mt][nt], akh[mt][0],akh[mt][1],akh[mt][2],akh[mt][3], l0,l1);
                    mma_bf16(acc[mt][nt], akl[mt][0],akl[mt][1],akl[mt][2],akl[mt][3], h0,h1);
                }
                if (wn == 0) {
                    mma_bf16(aks[mt], akh[mt][0],akh[mt][1],akh[mt][2],akh[mt][3], ONES, ONES);
                    mma_bf16(aks[mt], akl[mt][0],akl[mt][1],akl[mt][2],akl[mt][3], ONES, ONES);
                }
            }
        }
        __syncthreads();
        if (it + 2 < NS) issue(st, (it+2)*32);
        st ^= 1;
    }

    // epilogue: bounce KV[d][e] fp32 through smem, write KVT split + Ksum
    __syncthreads();
    float* KVs = (float*)smem;
    const int P = 68;
    #pragma unroll
    for (int mt = 0; mt < 2; mt++)
        #pragma unroll
        for (int nt = 0; nt < 4; nt++) {
            int d0 = wm + mt*16 + (lane >> 2);
            int e0 = wn + nt*8 + (lane & 3)*2;
            KVs[d0*P + e0]     = acc[mt][nt][0];
            KVs[d0*P + e0 + 1] = acc[mt][nt][1];
            KVs[(d0+8)*P + e0]     = acc[mt][nt][2];
            KVs[(d0+8)*P + e0 + 1] = acc[mt][nt][3];
        }
    if (wn == 0 && (lane & 3) == 0) {
        #pragma unroll
        for (int mt = 0; mt < 2; mt++) {
            int d0 = wm + mt*16 + (lane >> 2);
            Ksumg[bh*HDIM + d0]     = aks[mt][0];
            Ksumg[bh*HDIM + d0 + 8] = aks[mt][2];
        }
    }
    __syncthreads();
    int e = tid >> 1, dh = (tid & 1) * 32;
    #pragma unroll
    for (int j = 0; j < 32; j += 2) {
        int d = dh + j;
        float v0 = KVs[d*P + e], v1 = KVs[(d+1)*P + e];
        __nv_bfloat16 h0,l0,h1,l1;
        split2(v0,h0,l0); split2(v1,h1,l1);
        size_t idx = (size_t)bh*HDIM*HDIM + (size_t)e*HDIM + d;
        *(uint32_t*)&KVTh[idx] = pack2(h0,h1);
        *(uint32_t*)&KVTl[idx] = pack2(l0,l1);
    }
}

// ---------------- qattn_t: attn = z * (Q @ KV), tensor, split output -------
#define QAP 144
#define QSM (2*128*QAP + 2*64*QAP + 256 + 512)   // 55,... see offsets

__global__ __launch_bounds__(256) void qattn_t(
    const __nv_bfloat16* __restrict__ Qh_, const __nv_bfloat16* __restrict__ Ql_,
    const __nv_bfloat16* __restrict__ KVTh, const __nv_bfloat16* __restrict__ KVTl,
    const float* __restrict__ Ksumg,
    __nv_bfloat16* __restrict__ AttH, __nv_bfloat16* __restrict__ AttL)
{
    extern __shared__ __align__(16) char smem[];
    uint32_t sb = s2u(smem);
    int tid = threadIdx.x;
    int bh  = blockIdx.y;
    int b   = bh >> 4, h = bh & 15;
    int n0  = blockIdx.x * 128;
    const size_t qb = (size_t)b*SEQ*DMODEL + (size_t)n0*DMODEL + (size_t)h*HDIM;

    const uint32_t oQh = 0, oQl = 128*QAP, oBh = 2*128*QAP,
                   oBl = 2*128*QAP + 64*QAP,
                   oKs = 2*128*QAP + 2*64*QAP,
                   oZ  = oKs + 256;

    #pragma unroll
    for (int i = 0; i < 4; i++) {
        int cid = tid + i*256; int r = cid >> 3, c = cid & 7;
        size_t go = qb + (size_t)r*DMODEL + c*8;
        cp16(sb + oQh + r*QAP + c*16, Qh_ + go);
        cp16(sb + oQl + r*QAP + c*16, Ql_ + go);
    }
    #pragma unroll
    for (int i = 0; i < 2; i++) {
        int cid = tid + i*256; int r = cid >> 3, c = cid & 7;
        size_t go = (size_t)bh*HDIM*HDIM + (size_t)r*HDIM + c*8;
        cp16(sb + oBh + r*QAP + c*16, KVTh + go);
        cp16(sb + oBl + r*QAP + c*16, KVTl + go);
    }
    if (tid < 16) cp16(sb + oKs + tid*16, Ksumg + bh*HDIM + tid*4);
    cp_commit(); cp_wait<0>(); __syncthreads();

    // z = 1/(Q . Ksum) per row (2 threads/row)
    {
        int row = tid >> 1, hf = (tid & 1) * 32;
        const __nv_bfloat16* qh = (const __nv_bfloat16*)(smem + oQh + row*QAP) + hf;
        const __nv_bfloat16* ql = (const __nv_bfloat16*)(smem + oQl + row*QAP) + hf;
        const float* ks = (const float*)(smem + oKs) + hf;
        float s = 0.f;
        #pragma unroll
        for (int j = 0; j < 32; j++) {
            float q = __bfloat162float(qh[j]) + __bfloat162float(ql[j]);
            s += q * ks[j];
        }
        s += __shfl_xor_sync(0xFFFFFFFFu, s, 1);
        if ((tid & 1) == 0) ((float*)(smem + oZ))[row] = 1.f / s;
    }
    __syncthreads();

    int w = tid >> 5, lane = tid & 31;
    int wm = (w & 3) * 32, wn = (w >> 2) * 32;
    uint32_t aA = (uint32_t)((wm + (lane & 15))*QAP + (lane >> 4)*16);
    uint32_t aB = (uint32_t)((wn + (lane & 7) + (lane >> 4)*8)*QAP + ((lane >> 3) & 1)*16);

    float acc[2][4][4] = {};
    #pragma unroll
    for (int ks2 = 0; ks2 < 4; ks2++) {
        uint32_t ko = (uint32_t)ks2 * 32;
        uint32_t aqh[2][4], aql[2][4], bkh[2][4], bkl[2][4];
        #pragma unroll
        for (int mt = 0; mt < 2; mt++) {
            ldm_x4(aqh[mt], sb + oQh + aA + mt*16*QAP + ko);
            ldm_x4(aql[mt], sb + oQl + aA + mt*16*QAP + ko);
        }
        #pragma unroll
        for (int et = 0; et < 2; et++) {
            ldm_x4(bkh[et], sb + oBh + aB + et*16*QAP + ko);
            ldm_x4(bkl[et], sb + oBl + aB + et*16*QAP + ko);
        }
        #pragma unroll
        for (int mt = 0; mt < 2; mt++)
            #pragma unroll
            for (int nt = 0; nt < 4; nt++) {
                uint32_t h0 = bkh[nt>>1][(nt&1)*2], h1 = bkh[nt>>1][(nt&1)*2+1];
                uint32_t l0 = bkl[nt>>1][(nt&1)*2], l1 = bkl[nt>>1][(nt&1)*2+1];
                mma_bf16(acc[mt][nt], aqh[mt][0],aqh[mt][1],aqh[mt][2],aqh[mt][3], h0,h1);
                mma_bf16(acc[mt][nt], aqh[mt][0],aqh[mt][1],aqh[mt][2],aqh[mt][3], l0,l1);
                mma_bf16(acc[mt][nt], aql[mt][0],aql[mt][1],aql[mt][2],aql[mt][3], h0,h1);
            }
    }

    const float* zs = (const float*)(smem + oZ);
    #pragma unroll
    for (int mt = 0; mt < 2; mt++)
        #pragma unroll
        for (int nt = 0; nt < 4; nt++) {
            int r0 = wm + mt*16 + (lane >> 2);
            int e0 = wn + nt*8 + (lane & 3)*2;
            #pragma unroll
            for (int hg = 0; hg < 2; hg++) {
                int rr = r0 + hg*8;
                float z = zs[rr];
                float v0 = acc[mt][nt][hg*2+0] * z;
                float v1 = acc[mt][nt][hg*2+1] * z;
                __nv_bfloat16 h0,l0,h1,l1;
                split2(v0,h0,l0); split2(v1,h1,l1);
                size_t idx = qb + (size_t)rr*DMODEL + e0;
                *(uint32_t*)&AttH[idx] = pack2(h0,h1);
                *(uint32_t*)&AttL[idx] = pack2(l0,l1);
            }
        }
}

// ---------------- LayerNorm over D=1024 ------------------------------------
__global__ __launch_bounds__(256) void ln_k(
    const float* __restrict__ Y, const float* __restrict__ gamma,
    const float* __restrict__ beta, float* __restrict__ out)
{
    int row = blockIdx.x;
    int tid = threadIdx.x;
    float4 v = *(const float4*)&Y[(size_t)row*DMODEL + tid*4];
    float s  = v.x + v.y + v.z + v.w;
    float sq = v.x*v.x + v.y*v.y + v.z*v.z + v.w*v.w;
    #pragma unroll
    for (int o = 16; o > 0; o >>= 1) {
        s  += __shfl_xor_sync(0xFFFFFFFFu, s,  o);
        sq += __shfl_xor_sync(0xFFFFFFFFu, sq, o);
    }
    __shared__ float ss[8], ssq[8];
    int w = tid >> 5, l = tid & 31;
    if (l == 0) { ss[w] = s; ssq[w] = sq; }
    __syncthreads();
    if (tid == 0) {
        float S = 0.f, SQ = 0.f;
        #pragma unroll
        for (int i = 0; i < 8; i++) { S += ss[i]; SQ += ssq[i]; }
        ss[0] = S; ssq[0] = SQ;
    }
    __syncthreads();
    float mu  = ss[0] * (1.f/1024.f);
    float var = ssq[0] * (1.f/1024.f) - mu*mu;
    float inv = rsqrtf(var + 1e-3f);
    float4 gm = *(const float4*)&gamma[tid*4];
    float4 be = *(const float4*)&beta[tid*4];
    float4 o;
    o.x = (v.x - mu)*inv*gm.x + be.x;
    o.y = (v.y - mu)*inv*gm.y + be.y;
    o.z = (v.z - mu)*inv*gm.z + be.z;
    o.w = (v.w - mu)*inv*gm.w + be.w;
    *(float4*)&out[(size_t)row*DMODEL + tid*4] = o;
}

// ---------------- host entry ------------------------------------------------
extern "C" void kernel_launch(void* const* d_in, const int* in_sizes, int n_in,
                              void* d_out, int out_size)
{
    const float* x     = (const float*)d_in[0];
    const float* Wq    = (const float*)d_in[1];
    const float* bq    = (const float*)d_in[2];
    const float* Wk    = (const float*)d_in[3];
    const float* bk    = (const float*)d_in[4];
    const float* Wv    = (const float*)d_in[5];
    const float* bv    = (const float*)d_in[6];
    const float* Wo    = (const float*)d_in[7];
    const float* bo    = (const float*)d_in[8];
    const float* gamma = (const float*)d_in[9];
    const float* beta  = (const float*)d_in[10];
    float* out = (float*)d_out;

    float *Y, *Ksum;
    __nv_bfloat16 *Ah, *Al, *Qh, *Ql, *Kh, *Kl, *Vh, *Vl, *WTh, *WTl, *KVTh, *KVTl;
    cudaGetSymbolAddress((void**)&Y,    g_Y);
    cudaGetSymbolAddress((void**)&Ah,   g_Ah);
    cudaGetSymbolAddress((void**)&Al,   g_Al);
    cudaGetSymbolAddress((void**)&Qh,   g_Qh);
    cudaGetSymbolAddress((void**)&Ql,   g_Ql);
    cudaGetSymbolAddress((void**)&Kh,   g_Kh);
    cudaGetSymbolAddress((void**)&Kl,   g_Kl);
    cudaGetSymbolAddress((void**)&Vh,   g_Vh);
    cudaGetSymbolAddress((void**)&Vl,   g_Vl);
    cudaGetSymbolAddress((void**)&WTh,  g_WTh);
    cudaGetSymbolAddress((void**)&WTl,  g_WTl);
    cudaGetSymbolAddress((void**)&KVTh, g_KVTh);
    cudaGetSymbolAddress((void**)&KVTl, g_KVTl);
    cudaGetSymbolAddress((void**)&Ksum, g_Ksum);

    cudaFuncSetAttribute(gemm_qkv, cudaFuncAttributeMaxDynamicSharedMemorySize, GSMEM);
    cudaFuncSetAttribute(gemm_out, cudaFuncAttributeMaxDynamicSharedMemorySize, GSMEM);
    cudaFuncSetAttribute(qattn_t,  cudaFuncAttributeMaxDynamicSharedMemorySize, QSM);

    const size_t WSZ = (size_t)DMODEL*DMODEL;
    dim3 gqkv(DMODEL/BN, MTOT/BM, 3);
    dim3 gout(DMODEL/BN, MTOT/BM);
    dim3 tb(32, 8);
    dim3 tg4(DMODEL/32, DMODEL/32, 4);
    const int N4 = MTOT*DMODEL/4;

    split_rm<<<2048, 256>>>(x, Ah, Al, N4);
    split_tr4<<<tg4, tb>>>(Wq, Wk, Wv, Wo, WTh, WTl);

    gemm_qkv<<<gqkv, 256, GSMEM>>>(Ah, Al, WTh, WTl, bq, bk, bv,
                                   Qh, Ql, Kh, Kl, Vh, Vl);

    kv_ksum_t<<<BH, 128>>>(Kh, Kl, Vh, Vl, KVTh, KVTl, Ksum);
    qattn_t<<<dim3(SEQ/128, BH), 256, QSM>>>(Qh, Ql, KVTh, KVTl, Ksum, Ah, Al);

    gemm_out<<<gout, 256, GSMEM>>>(Ah, Al, WTh + 3*WSZ, WTl + 3*WSZ, bo, x, Y);

    ln_k<<<MTOT, 256>>>(Y, gamma, beta, out);
}